// round 8
// baseline (speedup 1.0000x reference)
#include <cuda_runtime.h>
#include <cuda_fp16.h>
#include <math.h>
#include <stdint.h>

#define BB 4
#define NN 4096
#define DD 256
#define MTOT (BB*NN)          // 16384
#define KAUG 768              // 3 x 256 split-fp16 augmented K (Qm projection)
#define SCALE_F 0.17677669529663689f

// ---------------- static device scratch ------------------------------------
__device__ __half g_Aaug[(size_t)MTOT*KAUG];   // x augmented
__device__ __half g_yh  [(size_t)MTOT*DD];     // y rounded to fp16 (cheap K)
__device__ float  g_Qm  [(size_t)MTOT*DD];     // x . (Wq Wk^T)  (fp32 "exact")
__device__ float  g_M   [(size_t)DD*DD];       // Wq Wk^T
__device__ float  g_Wvp [(size_t)DD*DD];       // Wv Wp
__device__ __half g_WtM [(size_t)DD*KAUG];     // M split, B-style
__device__ int    g_cnt;
__device__ int    g_list[MTOT];

// ---------------- PTX helpers ----------------------------------------------
__device__ __forceinline__ uint32_t smem_u32(const void* p){
    uint32_t a;
    asm("{ .reg .u64 t; cvta.to.shared.u64 t, %1; cvt.u32.u64 %0, t; }" : "=r"(a) : "l"(p));
    return a;
}
#define CP16(dst, src) \
    asm volatile("cp.async.cg.shared.global [%0], [%1], 16;" :: "r"(dst), "l"(src) : "memory")
#define CPC()  asm volatile("cp.async.commit_group;" ::: "memory")
#define CPW0() asm volatile("cp.async.wait_group 0;" ::: "memory")
#define CPW2() asm volatile("cp.async.wait_group 2;" ::: "memory")

__device__ __forceinline__ void ldsm4(uint32_t a, uint32_t& r0, uint32_t& r1,
                                      uint32_t& r2, uint32_t& r3){
    asm volatile("ldmatrix.sync.aligned.m8n8.x4.shared.b16 {%0,%1,%2,%3}, [%4];"
        : "=r"(r0), "=r"(r1), "=r"(r2), "=r"(r3) : "r"(a));
}
__device__ __forceinline__ void mma16816(float* c,
        uint32_t a0, uint32_t a1, uint32_t a2, uint32_t a3,
        uint32_t b0, uint32_t b1){
    asm volatile("mma.sync.aligned.m16n8k16.row.col.f32.f16.f16.f32 "
        "{%0,%1,%2,%3}, {%4,%5,%6,%7}, {%8,%9}, {%0,%1,%2,%3};"
        : "+f"(c[0]), "+f"(c[1]), "+f"(c[2]), "+f"(c[3])
        : "r"(a0), "r"(a1), "r"(a2), "r"(a3), "r"(b0), "r"(b1));
}

// ---------------- small fp32 GEMMs (exact-class) ----------------------------
// C[M,256] = A[M,256] @ W[256,256]
__global__ __launch_bounds__(256) void gemm256(const float* __restrict__ A,
                                               const float* __restrict__ W,
                                               float* __restrict__ C)
{
    __shared__ float As[64][17];
    __shared__ float Ws[16][64];
    const int t  = threadIdx.x;
    const int tx = t & 15, ty = t >> 4;
    const int m0 = blockIdx.x * 64, n0 = blockIdx.y * 64;
    const int lr = t >> 2, lc = (t & 3) * 4;
    float acc[4][4] = {};
    for (int kk = 0; kk < 256; kk += 16) {
        float4 av = *(const float4*)(A + (size_t)(m0 + lr) * 256 + kk + lc);
        As[lr][lc+0]=av.x; As[lr][lc+1]=av.y; As[lr][lc+2]=av.z; As[lr][lc+3]=av.w;
        float4 wv = *(const float4*)(W + (size_t)(kk + ty) * 256 + n0 + tx * 4);
        *(float4*)&Ws[ty][tx*4] = wv;
        __syncthreads();
        #pragma unroll
        for (int c = 0; c < 16; c++) {
            float a0=As[ty*4+0][c], a1=As[ty*4+1][c], a2=As[ty*4+2][c], a3=As[ty*4+3][c];
            float4 w = *(const float4*)&Ws[c][tx*4];
            acc[0][0]+=a0*w.x; acc[0][1]+=a0*w.y; acc[0][2]+=a0*w.z; acc[0][3]+=a0*w.w;
            acc[1][0]+=a1*w.x; acc[1][1]+=a1*w.y; acc[1][2]+=a1*w.z; acc[1][3]+=a1*w.w;
            acc[2][0]+=a2*w.x; acc[2][1]+=a2*w.y; acc[2][2]+=a2*w.z; acc[2][3]+=a2*w.w;
            acc[3][0]+=a3*w.x; acc[3][1]+=a3*w.y; acc[3][2]+=a3*w.z; acc[3][3]+=a3*w.w;
        }
        __syncthreads();
    }
    #pragma unroll
    for (int j = 0; j < 4; j++) {
        float4 o = make_float4(acc[j][0], acc[j][1], acc[j][2], acc[j][3]);
        *(float4*)(C + (size_t)(m0 + ty*4 + j) * 256 + n0 + tx*4) = o;
    }
}

// C[M,256] = A[M,256] @ B[256,256]^T   (C[i][j] = sum_k A[i][k] B[j][k])
__global__ __launch_bounds__(256) void gemm256_nt(const float* __restrict__ A,
                                                  const float* __restrict__ Bm,
                                                  float* __restrict__ C)
{
    __shared__ float As[64][17];
    __shared__ float Ws[16][64];
    const int t  = threadIdx.x;
    const int tx = t & 15, ty = t >> 4;
    const int m0 = blockIdx.x * 64, n0 = blockIdx.y * 64;
    const int lr = t >> 2, lc = (t & 3) * 4;
    float acc[4][4] = {};
    for (int kk = 0; kk < 256; kk += 16) {
        float4 av = *(const float4*)(A + (size_t)(m0 + lr) * 256 + kk + lc);
        As[lr][lc+0]=av.x; As[lr][lc+1]=av.y; As[lr][lc+2]=av.z; As[lr][lc+3]=av.w;
        #pragma unroll
        for (int i = 0; i < 4; i++)
            Ws[ty][tx*4+i] = Bm[(size_t)(n0 + tx*4 + i) * 256 + kk + ty];
        __syncthreads();
        #pragma unroll
        for (int c = 0; c < 16; c++) {
            float a0=As[ty*4+0][c], a1=As[ty*4+1][c], a2=As[ty*4+2][c], a3=As[ty*4+3][c];
            float4 w = *(const float4*)&Ws[c][tx*4];
            acc[0][0]+=a0*w.x; acc[0][1]+=a0*w.y; acc[0][2]+=a0*w.z; acc[0][3]+=a0*w.w;
            acc[1][0]+=a1*w.x; acc[1][1]+=a1*w.y; acc[1][2]+=a1*w.z; acc[1][3]+=a1*w.w;
            acc[2][0]+=a2*w.x; acc[2][1]+=a2*w.y; acc[2][2]+=a2*w.z; acc[2][3]+=a2*w.w;
            acc[3][0]+=a3*w.x; acc[3][1]+=a3*w.y; acc[3][2]+=a3*w.z; acc[3][3]+=a3*w.w;
        }
        __syncthreads();
    }
    #pragma unroll
    for (int j = 0; j < 4; j++) {
        float4 o = make_float4(acc[j][0], acc[j][1], acc[j][2], acc[j][3]);
        *(float4*)(C + (size_t)(m0 + ty*4 + j) * 256 + n0 + tx*4) = o;
    }
}

// ---------------- prep kernels ----------------------------------------------
// A-side augmentation: [h | h | l]
__global__ void prep_aug(const float* __restrict__ src, __half* __restrict__ dst)
{
    const size_t total = (size_t)MTOT * 64;
    for (size_t i = (size_t)blockIdx.x*blockDim.x + threadIdx.x; i < total;
         i += (size_t)gridDim.x*blockDim.x) {
        size_t row = i >> 6; int c4 = (int)(i & 63);
        float4 v = ((const float4*)src)[i];
        __half h0=__float2half_rn(v.x), h1=__float2half_rn(v.y);
        __half h2=__float2half_rn(v.z), h3=__float2half_rn(v.w);
        __half2 H01=__halves2half2(h0,h1), H23=__halves2half2(h2,h3);
        __half2 L01=__halves2half2(__float2half_rn(v.x-__half2float(h0)),
                                   __float2half_rn(v.y-__half2float(h1)));
        __half2 L23=__halves2half2(__float2half_rn(v.z-__half2float(h2)),
                                   __float2half_rn(v.w-__half2float(h3)));
        __half* base = dst + row*KAUG + c4*4;
        ((__half2*)base)[0] = H01; ((__half2*)base)[1] = H23;
        ((__half2*)(base+256))[0] = H01; ((__half2*)(base+256))[1] = H23;
        ((__half2*)(base+512))[0] = L01; ((__half2*)(base+512))[1] = L23;
    }
}

// plain fp32 -> fp16 round (cheap-pass K = y)
__global__ void prep_h(const float* __restrict__ src, __half* __restrict__ dst)
{
    const size_t total = (size_t)MTOT * 64;
    for (size_t i = (size_t)blockIdx.x*blockDim.x + threadIdx.x; i < total;
         i += (size_t)gridDim.x*blockDim.x) {
        float4 v = ((const float4*)src)[i];
        ((__half2*)dst)[i*2]   = __halves2half2(__float2half_rn(v.x), __float2half_rn(v.y));
        ((__half2*)dst)[i*2+1] = __halves2half2(__float2half_rn(v.z), __float2half_rn(v.w));
    }
}

// W[256k x 256n] fp32 -> Wt[256n x 768k] half, B-style split [h | l | h]
__global__ void prep_wt(const float* __restrict__ W, __half* __restrict__ Wt)
{
    int k = blockIdx.x;
    int n = threadIdx.x;
    float v = W[(size_t)k*DD + n];
    __half h = __float2half_rn(v);
    __half l = __float2half_rn(v - __half2float(h));
    Wt[(size_t)n*KAUG + k]       = h;
    Wt[(size_t)n*KAUG + 256 + k] = l;
    Wt[(size_t)n*KAUG + 512 + k] = h;
}

// ---------------- HMMA GEMM: C[M,256] = Aaug[M,768] . Wt[256,768]^T ----------
__global__ __launch_bounds__(256) void hgemm(const __half* __restrict__ A,
                                             const __half* __restrict__ Bw,
                                             float* __restrict__ C)
{
    __shared__ __align__(16) char sm[4*10240];
    const uint32_t sb = smem_u32(sm);
    const int t = threadIdx.x, lane = t & 31, wid = t >> 5;
    const int wm = wid >> 1, wn = wid & 1;
    const int m0 = blockIdx.x * 128, n0 = blockIdx.y * 128;

    float c[2][8][4] = {};
    {
        #pragma unroll
        for (int i = 0; i < 2; i++) {
            int sidx = t*2 + i; int row = sidx >> 2, seg = sidx & 3;
            CP16(sb + row*80 + seg*16,           A  + (size_t)(m0+row)*KAUG + seg*8);
            CP16(sb + 20480 + row*80 + seg*16,   Bw + (size_t)(n0+row)*KAUG + seg*8);
        }
        CPC();
    }
    const uint32_t aRowOff = (uint32_t)(wm*32 + (lane&15))*80 + ((lane>>4)&1)*16;
    const uint32_t bRowOff = (uint32_t)(wn*64 + (lane&7) + ((lane>>3)&1)*8)*80
                           + ((lane>>4)&1)*16;

    for (int ch = 0; ch < 24; ch++) {
        int buf = ch & 1;
        CPW0();
        __syncthreads();
        if (ch + 1 < 24) {
            int nb = buf ^ 1;
            #pragma unroll
            for (int i = 0; i < 2; i++) {
                int sidx = t*2 + i; int row = sidx >> 2, seg = sidx & 3;
                CP16(sb + nb*10240 + row*80 + seg*16,
                     A  + (size_t)(m0+row)*KAUG + (ch+1)*32 + seg*8);
                CP16(sb + 20480 + nb*10240 + row*80 + seg*16,
                     Bw + (size_t)(n0+row)*KAUG + (ch+1)*32 + seg*8);
            }
            CPC();
        }
        uint32_t aBase = sb + buf*10240 + aRowOff;
        uint32_t bBase = sb + 20480 + buf*10240 + bRowOff;
        #pragma unroll
        for (int ks = 0; ks < 2; ks++) {
            uint32_t a0,a1,a2,a3,a4,a5,a6,a7;
            ldsm4(aBase + ks*32,            a0,a1,a2,a3);
            ldsm4(aBase + 16*80 + ks*32,    a4,a5,a6,a7);
            #pragma unroll
            for (int p = 0; p < 4; p++) {
                uint32_t b0,b1,b2,b3;
                ldsm4(bBase + p*1280 + ks*32, b0,b1,b2,b3);
                mma16816(c[0][2*p+0], a0,a1,a2,a3, b0,b2);
                mma16816(c[0][2*p+1], a0,a1,a2,a3, b1,b3);
                mma16816(c[1][2*p+0], a4,a5,a6,a7, b0,b2);
                mma16816(c[1][2*p+1], a4,a5,a6,a7, b1,b3);
            }
        }
    }
    #pragma unroll
    for (int mi = 0; mi < 2; mi++)
        #pragma unroll
        for (int ni = 0; ni < 8; ni++) {
            int row = m0 + wm*32 + mi*16 + (lane>>2);
            int col = n0 + wn*64 + ni*8 + 2*(lane&3);
            *(float2*)(C + (size_t)row*DD + col) =
                make_float2(c[mi][ni][0], c[mi][ni][1]);
            *(float2*)(C + (size_t)(row+8)*DD + col) =
                make_float2(c[mi][ni][2], c[mi][ni][3]);
        }
}

// ---------------- cheap 1-term attention gate --------------------------------
// per CTA: 128 q-rows x 4096 keys. K chunks of 64 cols, 4-stage cp.async.
#define AQ_STRIDE  528                        // 256 half + 16B pad
#define AQS_BYTES  (128*AQ_STRIDE)            // 67584
#define KB_OFF     AQS_BYTES
#define KST        (128*144)                  // 64 cols (128B) + 16 pad per row
#define NST        4
#define MRG_OFF    (KB_OFF + NST*KST)         // 141312
#define SMEM_ATTN  (MRG_OFF + 4096)

__global__ __launch_bounds__(256) void attn_cheap(const float* __restrict__ Qg_,
        const __half* __restrict__ Khg, const float* __restrict__ bp,
        float* __restrict__ Og_)
{
    extern __shared__ __align__(128) char smem[];
    const uint32_t sb = smem_u32(smem);
    const int t = threadIdx.x, lane = t & 31, wid = t >> 5;
    const int wm = wid >> 1, wn = wid & 1;
    const int b = blockIdx.y, q0 = blockIdx.x * 128;

    const __half* Kb = Khg + (size_t)b*NN*DD;

    // prologue: stages 0,1,2 (kt=0, ch=idx)
    #pragma unroll
    for (int st = 0; st < 3; st++) {
        #pragma unroll
        for (int i = 0; i < 4; i++) {
            int sidx = t*4 + i; int row = sidx >> 3, seg = sidx & 7;
            CP16(sb + KB_OFF + st*KST + row*144 + seg*16,
                 Kb + (size_t)row*DD + st*64 + seg*8);
        }
        CPC();
    }

    // bp into smem merge region tail
    float* bp_s = (float*)(smem + MRG_OFF + 3072);   // 256 floats
    if (t < 64) ((float4*)bp_s)[t] = ((const float4*)bp)[t];

    // build Qh tile (pre-scaled fp16)
    const float* Qg = Qg_ + (size_t)(b*NN + q0)*DD;
    #pragma unroll 4
    for (int i = 0; i < 32; i++) {
        int e4 = t + i*256;
        int row = e4 >> 6, c4 = e4 & 63;
        float4 v = ((const float4*)Qg)[(size_t)row*64 + c4];
        __half2 H01 = __halves2half2(__float2half_rn(v.x*SCALE_F),
                                     __float2half_rn(v.y*SCALE_F));
        __half2 H23 = __halves2half2(__float2half_rn(v.z*SCALE_F),
                                     __float2half_rn(v.w*SCALE_F));
        char* base = smem + (size_t)row*AQ_STRIDE + (size_t)c4*8;
        *(__half2*)(base)   = H01;
        *(__half2*)(base+4) = H23;
    }

    float c[2][8][4] = {};
    float rm[4], rs[4];
    #pragma unroll
    for (int j = 0; j < 4; j++) { rm[j] = -3.0e38f; rs[j] = 0.f; }

    const uint32_t aRowOff = (uint32_t)(wm*32 + (lane&15))*AQ_STRIDE + ((lane>>4)&1)*16;
    const uint32_t bRowOff = (uint32_t)(wn*64 + (lane&7) + ((lane>>3)&1)*8)*144
                           + ((lane>>4)&1)*16;

    for (int idx = 0; idx < 128; idx++) {
        CPW2();                         // stage idx ready (<=2 pending)
        __syncthreads();
        if (idx + 3 < 128) {
            int nx = idx + 3, nkt = nx >> 2, nch = nx & 3, nb = nx & 3;
            #pragma unroll
            for (int i = 0; i < 4; i++) {
                int sidx = t*4 + i; int row = sidx >> 3, seg = sidx & 7;
                CP16(sb + KB_OFF + nb*KST + row*144 + seg*16,
                     Kb + (size_t)(nkt*128+row)*DD + nch*64 + seg*8);
            }
            CPC();
        }
        uint32_t aBase = sb + aRowOff + (uint32_t)(idx & 3)*128;
        uint32_t bBase = sb + KB_OFF + (idx & 3)*KST + bRowOff;
        #pragma unroll
        for (int ks = 0; ks < 4; ks++) {
            uint32_t a0,a1,a2,a3,a4,a5,a6,a7;
            ldsm4(aBase + ks*32,                  a0,a1,a2,a3);
            ldsm4(aBase + 16*AQ_STRIDE + ks*32,   a4,a5,a6,a7);
            #pragma unroll
            for (int p = 0; p < 4; p++) {
                uint32_t b0,b1,b2,b3;
                ldsm4(bBase + p*2304 + ks*32, b0,b1,b2,b3);
                mma16816(c[0][2*p+0], a0,a1,a2,a3, b0,b2);
                mma16816(c[0][2*p+1], a0,a1,a2,a3, b1,b3);
                mma16816(c[1][2*p+0], a4,a5,a6,a7, b0,b2);
                mma16816(c[1][2*p+1], a4,a5,a6,a7, b1,b3);
            }
        }
        if ((idx & 3) == 3) {
            // per-key-tile online (max, sumexp); no argmax needed
            #pragma unroll
            for (int j = 0; j < 4; j++) {
                int mi = j >> 1, hr = (j & 1) * 2;
                float tm = -3.0e38f;
                #pragma unroll
                for (int ni = 0; ni < 8; ni++)
                    tm = fmaxf(tm, fmaxf(c[mi][ni][hr], c[mi][ni][hr+1]));
                #pragma unroll
                for (int off = 1; off <= 2; off <<= 1)
                    tm = fmaxf(tm, __shfl_xor_sync(0xffffffffu, tm, off));
                float ts = 0.f;
                #pragma unroll
                for (int ni = 0; ni < 8; ni++) {
                    ts += __expf(c[mi][ni][hr]   - tm);
                    ts += __expf(c[mi][ni][hr+1] - tm);
                }
                #pragma unroll
                for (int off = 1; off <= 2; off <<= 1)
                    ts += __shfl_xor_sync(0xffffffffu, ts, off);
                if (tm > rm[j]) {
                    rs[j] = rs[j]*__expf(rm[j]-tm) + ts;
                    rm[j] = tm;
                } else {
                    rs[j] += ts*__expf(tm - rm[j]);
                }
            }
            #pragma unroll
            for (int mi = 0; mi < 2; mi++)
                #pragma unroll
                for (int ni = 0; ni < 8; ni++)
                    #pragma unroll
                    for (int r = 0; r < 4; r++) c[mi][ni][r] = 0.f;
        }
    }

    // ---- merge n-halves, gate ----
    float* m_arr = (float*)(smem + MRG_OFF);           // [256]
    float* s_arr = (float*)(smem + MRG_OFF + 1024);    // [256]
    int*   f_arr = (int*)  (smem + MRG_OFF + 2048);    // [128]
    if ((lane & 3) == 0) {
        #pragma unroll
        for (int j = 0; j < 4; j++) {
            int row = wm*32 + (j>>1)*16 + (j&1)*8 + (lane>>2);
            m_arr[wn*128 + row] = rm[j];
            s_arr[wn*128 + row] = rs[j];
        }
    }
    __syncthreads();
    if (t < 128) {
        float m0v = m_arr[t], m1v = m_arr[128+t];
        float s0  = s_arr[t], s1  = s_arr[128+t];
        float mm  = fmaxf(m0v, m1v);
        float ss  = s0*__expf(m0v-mm) + s1*__expf(m1v-mm);
        float pt  = 1.0f / ss;
        int flag = (pt < 0.5f);
        if (!flag) {
            int slot = atomicAdd(&g_cnt, 1);
            if (slot < MTOT) g_list[slot] = b*NN + q0 + t;
        }
        f_arr[t] = flag;
    }
    __syncthreads();

    // ---- write bp rows for gated-out rows ----
    float* Og = Og_ + (size_t)(b*NN + q0)*DD;
    #pragma unroll 4
    for (int i = 0; i < 32; i++) {
        int e4 = t + i*256;
        int row = e4 >> 6, c4 = e4 & 63;
        if (f_arr[row])
            ((float4*)Og)[(size_t)row*64 + c4] = ((float4*)bp_s)[c4];
    }
}

// ---------------- exact fp32 finalize for candidate rows --------------------
__global__ __launch_bounds__(256) void finalize_k(const float* __restrict__ Qm,
        const float* __restrict__ y, const float* __restrict__ x,
        const float* __restrict__ Wvp, const float* __restrict__ bp,
        float* __restrict__ O)
{
    __shared__ float s_sm[4096];
    __shared__ float q_sm[256];
    __shared__ float x_sm[256];
    __shared__ float red_m[8];
    __shared__ int   red_a[8];
    __shared__ float red_s[8];
    __shared__ double red_d[8];
    __shared__ float sh_m;
    __shared__ int   sh_a;
    __shared__ float sh_p;
    const int t = threadIdx.x, lane = t & 31, w = t >> 5;
    int cnt = g_cnt; if (cnt > MTOT) cnt = MTOT;

    for (int idx = blockIdx.x; idx < cnt; idx += gridDim.x) {
        int grow = g_list[idx];
        int b = grow >> 12;
        if (t < 64) ((float4*)q_sm)[t] = ((const float4*)(Qm + (size_t)grow*DD))[t];
        __syncthreads();

        const float* Kb = y + (size_t)b*NN*DD;
        float lm = -3.0e38f; int la = 0;
        for (int j = t; j < NN; j += 256) {
            const float4* kr = (const float4*)(Kb + (size_t)j*DD);
            float acc = 0.f;
            #pragma unroll
            for (int d = 0; d < 64; d++) {
                float4 kv = kr[d];
                float4 qv = ((const float4*)q_sm)[d];
                acc += qv.x*kv.x + qv.y*kv.y + qv.z*kv.z + qv.w*kv.w;
            }
            float s = acc * SCALE_F;
            s_sm[j] = s;
            if (s > lm) { lm = s; la = j; }
        }
        #pragma unroll
        for (int off = 16; off; off >>= 1) {
            float om = __shfl_xor_sync(0xffffffffu, lm, off);
            int   oa = __shfl_xor_sync(0xffffffffu, la, off);
            if (om > lm || (om == lm && oa < la)) { lm = om; la = oa; }
        }
        if (lane == 0) { red_m[w] = lm; red_a[w] = la; }
        __syncthreads();
        if (w == 0) {
            float m2 = (lane < 8) ? red_m[lane] : -3.0e38f;
            int   a2 = (lane < 8) ? red_a[lane] : 0;
            #pragma unroll
            for (int off = 4; off; off >>= 1) {
                float om = __shfl_xor_sync(0xffffffffu, m2, off);
                int   oa = __shfl_xor_sync(0xffffffffu, a2, off);
                if (om > m2 || (om == m2 && oa < a2)) { m2 = om; a2 = oa; }
            }
            if (lane == 0) { sh_m = m2; sh_a = a2; }
        }
        __syncthreads();
        float m = sh_m; int amax = sh_a;
        float ls = 0.f;
        for (int j = t; j < NN; j += 256) ls += __expf(s_sm[j] - m);
        #pragma unroll
        for (int off = 16; off; off >>= 1)
            ls += __shfl_xor_sync(0xffffffffu, ls, off);
        if (lane == 0) red_s[w] = ls;
        __syncthreads();
        if (t == 0) {
            float S = 0.f;
            #pragma unroll
            for (int i2 = 0; i2 < 8; i2++) S += red_s[i2];
            sh_p = 1.0f / S;
        }
        __syncthreads();
        float p = sh_p;

        // boundary guard: double-precision re-pass (expected 0 rows)
        if (fabsf(p - 0.6f) < 3e-4f) {
            double dls = 0.0;
            for (int j = t; j < NN; j += 256) {
                const float* kr = Kb + (size_t)j*DD;
                double acc = 0.0;
                #pragma unroll 8
                for (int d = 0; d < 256; d++)
                    acc += (double)q_sm[d] * (double)kr[d];
                dls += exp(acc * (double)SCALE_F - (double)m);
            }
            #pragma unroll
            for (int off = 16; off; off >>= 1)
                dls += __shfl_xor_sync(0xffffffffu, dls, off);
            if (lane == 0) red_d[w] = dls;
            __syncthreads();
            if (t == 0) {
                double S = 0.0;
                #pragma unroll
                for (int i2 = 0; i2 < 8; i2++) S += red_d[i2];
                sh_p = (float)(1.0 / S);
            }
            __syncthreads();
            p = sh_p;
        }

        if (p >= 0.6f) {
            if (t < 64)
                ((float4*)x_sm)[t] =
                    ((const float4*)(x + (size_t)(b*NN + amax)*DD))[t];
            __syncthreads();
            float acc = 0.f;
            #pragma unroll 8
            for (int k = 0; k < 256; k++)
                acc += x_sm[k] * Wvp[(size_t)k*DD + t];
            O[(size_t)grow*DD + t] = p * acc + bp[t];
        } else {
            O[(size_t)grow*DD + t] = bp[t];
        }
        __syncthreads();
    }
}

// ---------------------------------------------------------------------------
extern "C" void kernel_launch(void* const* d_in, const int* in_sizes, int n_in,
                              void* d_out, int out_size)
{
    const float* x  = (const float*)d_in[0];
    const float* y  = (const float*)d_in[1];
    const float* Wq = (const float*)d_in[2];
    const float* Wk = (const float*)d_in[3];
    const float* Wv = (const float*)d_in[4];
    const float* Wp = (const float*)d_in[5];
    const float* bp = (const float*)d_in[6];
    float* out = (float*)d_out;

    __half *Aaug, *yh, *WtM;
    float *Qm, *M, *Wvp;
    void* cntp;
    cudaGetSymbolAddress((void**)&Aaug, g_Aaug);
    cudaGetSymbolAddress((void**)&yh,   g_yh);
    cudaGetSymbolAddress((void**)&Qm,   g_Qm);
    cudaGetSymbolAddress((void**)&M,    g_M);
    cudaGetSymbolAddress((void**)&Wvp,  g_Wvp);
    cudaGetSymbolAddress((void**)&WtM,  g_WtM);
    cudaGetSymbolAddress(&cntp,         g_cnt);

    cudaFuncSetAttribute(attn_cheap,
                         cudaFuncAttributeMaxDynamicSharedMemorySize, SMEM_ATTN);

    cudaMemsetAsync(cntp, 0, sizeof(int));

    prep_h<<<2048, 256>>>(y, yh);                       // cheap K = fp16(y)
    gemm256_nt<<<dim3(4,4), 256>>>(Wq, Wk, M);          // M   = Wq Wk^T
    gemm256<<<dim3(4,4), 256>>>(Wv, Wp, Wvp);           // Wvp = Wv Wp
    prep_wt<<<256, 256>>>(M, WtM);
    prep_aug<<<2048, 256>>>(x, Aaug);
    hgemm<<<dim3(MTOT/128, DD/128), 256>>>(Aaug, WtM, Qm);   // Qm = x M (exact-class)

    attn_cheap<<<dim3(NN/128, BB), 256, SMEM_ATTN>>>(Qm, yh, bp, out);
    finalize_k<<<256, 256>>>(Qm, y, x, Wvp, bp, out);
}

// round 9
// speedup vs baseline: 1.4800x; 1.4800x over previous
#include <cuda_runtime.h>
#include <cuda_fp16.h>
#include <math.h>
#include <stdint.h>

#define BB 4
#define NN 4096
#define DD 256
#define MTOT (BB*NN)          // 16384
#define KAUG 768              // 3-term split for projection GEMMs
#define SCALE_F 0.17677669529663689f
#define BAND 1.5e-3f

// ---------------- static device scratch ------------------------------------
__device__ __half g_Aaug[(size_t)MTOT*KAUG];   // x augmented [h|h|l]
__device__ __half g_yh  [(size_t)MTOT*DD];     // y rounded to fp16 (attn K)
__device__ float  g_Qm  [(size_t)MTOT*DD];     // x . (Wq Wk^T)
__device__ float  g_VP  [(size_t)MTOT*DD];     // x . (Wv Wp)
__device__ float  g_M   [(size_t)DD*DD];       // Wq Wk^T
__device__ float  g_Wvp [(size_t)DD*DD];       // Wv Wp
__device__ __half g_Wt2 [(size_t)2*DD*KAUG];   // [M ; Wvp] split B-style, 512x768
__device__ int    g_cnt;
__device__ int    g_list[MTOT];

// ---------------- PTX helpers ----------------------------------------------
__device__ __forceinline__ uint32_t smem_u32(const void* p){
    uint32_t a;
    asm("{ .reg .u64 t; cvta.to.shared.u64 t, %1; cvt.u32.u64 %0, t; }" : "=r"(a) : "l"(p));
    return a;
}
#define CP16(dst, src) \
    asm volatile("cp.async.cg.shared.global [%0], [%1], 16;" :: "r"(dst), "l"(src) : "memory")
#define CPC()  asm volatile("cp.async.commit_group;" ::: "memory")
#define CPW0() asm volatile("cp.async.wait_group 0;" ::: "memory")

__device__ __forceinline__ void ldsm4(uint32_t a, uint32_t& r0, uint32_t& r1,
                                      uint32_t& r2, uint32_t& r3){
    asm volatile("ldmatrix.sync.aligned.m8n8.x4.shared.b16 {%0,%1,%2,%3}, [%4];"
        : "=r"(r0), "=r"(r1), "=r"(r2), "=r"(r3) : "r"(a));
}
__device__ __forceinline__ void mma16816(float* c,
        uint32_t a0, uint32_t a1, uint32_t a2, uint32_t a3,
        uint32_t b0, uint32_t b1){
    asm volatile("mma.sync.aligned.m16n8k16.row.col.f32.f16.f16.f32 "
        "{%0,%1,%2,%3}, {%4,%5,%6,%7}, {%8,%9}, {%0,%1,%2,%3};"
        : "+f"(c[0]), "+f"(c[1]), "+f"(c[2]), "+f"(c[3])
        : "r"(a0), "r"(a1), "r"(a2), "r"(a3), "r"(b0), "r"(b1));
}

// ---------------- small fp32 GEMMs (weights) --------------------------------
// C = A @ W  (256x256 each)
__global__ __launch_bounds__(256) void gemm256(const float* __restrict__ A,
                                               const float* __restrict__ W,
                                               float* __restrict__ C)
{
    __shared__ float As[64][17];
    __shared__ float Ws[16][64];
    const int t  = threadIdx.x;
    const int tx = t & 15, ty = t >> 4;
    const int m0 = blockIdx.x * 64, n0 = blockIdx.y * 64;
    const int lr = t >> 2, lc = (t & 3) * 4;
    float acc[4][4] = {};
    for (int kk = 0; kk < 256; kk += 16) {
        float4 av = *(const float4*)(A + (size_t)(m0 + lr) * 256 + kk + lc);
        As[lr][lc+0]=av.x; As[lr][lc+1]=av.y; As[lr][lc+2]=av.z; As[lr][lc+3]=av.w;
        float4 wv = *(const float4*)(W + (size_t)(kk + ty) * 256 + n0 + tx * 4);
        *(float4*)&Ws[ty][tx*4] = wv;
        __syncthreads();
        #pragma unroll
        for (int c = 0; c < 16; c++) {
            float a0=As[ty*4+0][c], a1=As[ty*4+1][c], a2=As[ty*4+2][c], a3=As[ty*4+3][c];
            float4 w = *(const float4*)&Ws[c][tx*4];
            acc[0][0]+=a0*w.x; acc[0][1]+=a0*w.y; acc[0][2]+=a0*w.z; acc[0][3]+=a0*w.w;
            acc[1][0]+=a1*w.x; acc[1][1]+=a1*w.y; acc[1][2]+=a1*w.z; acc[1][3]+=a1*w.w;
            acc[2][0]+=a2*w.x; acc[2][1]+=a2*w.y; acc[2][2]+=a2*w.z; acc[2][3]+=a2*w.w;
            acc[3][0]+=a3*w.x; acc[3][1]+=a3*w.y; acc[3][2]+=a3*w.z; acc[3][3]+=a3*w.w;
        }
        __syncthreads();
    }
    #pragma unroll
    for (int j = 0; j < 4; j++) {
        float4 o = make_float4(acc[j][0], acc[j][1], acc[j][2], acc[j][3]);
        *(float4*)(C + (size_t)(m0 + ty*4 + j) * 256 + n0 + tx*4) = o;
    }
}

// C = A @ B^T
__global__ __launch_bounds__(256) void gemm256_nt(const float* __restrict__ A,
                                                  const float* __restrict__ Bm,
                                                  float* __restrict__ C)
{
    __shared__ float As[64][17];
    __shared__ float Ws[16][64];
    const int t  = threadIdx.x;
    const int tx = t & 15, ty = t >> 4;
    const int m0 = blockIdx.x * 64, n0 = blockIdx.y * 64;
    const int lr = t >> 2, lc = (t & 3) * 4;
    float acc[4][4] = {};
    for (int kk = 0; kk < 256; kk += 16) {
        float4 av = *(const float4*)(A + (size_t)(m0 + lr) * 256 + kk + lc);
        As[lr][lc+0]=av.x; As[lr][lc+1]=av.y; As[lr][lc+2]=av.z; As[lr][lc+3]=av.w;
        #pragma unroll
        for (int i = 0; i < 4; i++)
            Ws[ty][tx*4+i] = Bm[(size_t)(n0 + tx*4 + i) * 256 + kk + ty];
        __syncthreads();
        #pragma unroll
        for (int c = 0; c < 16; c++) {
            float a0=As[ty*4+0][c], a1=As[ty*4+1][c], a2=As[ty*4+2][c], a3=As[ty*4+3][c];
            float4 w = *(const float4*)&Ws[c][tx*4];
            acc[0][0]+=a0*w.x; acc[0][1]+=a0*w.y; acc[0][2]+=a0*w.z; acc[0][3]+=a0*w.w;
            acc[1][0]+=a1*w.x; acc[1][1]+=a1*w.y; acc[1][2]+=a1*w.z; acc[1][3]+=a1*w.w;
            acc[2][0]+=a2*w.x; acc[2][1]+=a2*w.y; acc[2][2]+=a2*w.z; acc[2][3]+=a2*w.w;
            acc[3][0]+=a3*w.x; acc[3][1]+=a3*w.y; acc[3][2]+=a3*w.z; acc[3][3]+=a3*w.w;
        }
        __syncthreads();
    }
    #pragma unroll
    for (int j = 0; j < 4; j++) {
        float4 o = make_float4(acc[j][0], acc[j][1], acc[j][2], acc[j][3]);
        *(float4*)(C + (size_t)(m0 + ty*4 + j) * 256 + n0 + tx*4) = o;
    }
}

// ---------------- prep kernels ----------------------------------------------
// A-side augmentation of x: [h | h | l]
__global__ void prep_aug(const float* __restrict__ src, __half* __restrict__ dst)
{
    const size_t total = (size_t)MTOT * 64;
    for (size_t i = (size_t)blockIdx.x*blockDim.x + threadIdx.x; i < total;
         i += (size_t)gridDim.x*blockDim.x) {
        size_t row = i >> 6; int c4 = (int)(i & 63);
        float4 v = ((const float4*)src)[i];
        __half h0=__float2half_rn(v.x), h1=__float2half_rn(v.y);
        __half h2=__float2half_rn(v.z), h3=__float2half_rn(v.w);
        __half2 H01=__halves2half2(h0,h1), H23=__halves2half2(h2,h3);
        __half2 L01=__halves2half2(__float2half_rn(v.x-__half2float(h0)),
                                   __float2half_rn(v.y-__half2float(h1)));
        __half2 L23=__halves2half2(__float2half_rn(v.z-__half2float(h2)),
                                   __float2half_rn(v.w-__half2float(h3)));
        __half* base = dst + row*KAUG + c4*4;
        ((__half2*)base)[0] = H01; ((__half2*)base)[1] = H23;
        ((__half2*)(base+256))[0] = H01; ((__half2*)(base+256))[1] = H23;
        ((__half2*)(base+512))[0] = L01; ((__half2*)(base+512))[1] = L23;
    }
}

// y -> fp16
__global__ void prep_h(const float* __restrict__ src, __half* __restrict__ dst)
{
    const size_t total = (size_t)MTOT * 64;
    for (size_t i = (size_t)blockIdx.x*blockDim.x + threadIdx.x; i < total;
         i += (size_t)gridDim.x*blockDim.x) {
        float4 v = ((const float4*)src)[i];
        ((__half2*)dst)[i*2]   = __halves2half2(__float2half_rn(v.x), __float2half_rn(v.y));
        ((__half2*)dst)[i*2+1] = __halves2half2(__float2half_rn(v.z), __float2half_rn(v.w));
    }
}

// split both M and Wvp into one 512x768 B-style matrix [h | l | h]
__global__ void prep_wt2(const float* __restrict__ M, const float* __restrict__ Wvp,
                         __half* __restrict__ Wt2)
{
    const float* W = blockIdx.y ? Wvp : M;
    int rowoff = blockIdx.y * 256;
    int k = blockIdx.x;
    int n = threadIdx.x;
    float v = W[(size_t)k*DD + n];
    __half h = __float2half_rn(v);
    __half l = __float2half_rn(v - __half2float(h));
    __half* dst = Wt2 + (size_t)(n + rowoff)*KAUG;
    dst[k]       = h;
    dst[256 + k] = l;
    dst[512 + k] = h;
}

// ---------------- fused HMMA GEMM: [Qm | VP] = Aaug . Wt2^T -----------------
__global__ __launch_bounds__(256) void hgemm2(const __half* __restrict__ A,
                                              const __half* __restrict__ Bw,
                                              float* __restrict__ Qm,
                                              float* __restrict__ VP)
{
    __shared__ __align__(16) char sm[4*10240];
    const uint32_t sb = smem_u32(sm);
    const int t = threadIdx.x, lane = t & 31, wid = t >> 5;
    const int wm = wid >> 1, wn = wid & 1;
    const int m0 = blockIdx.x * 128, n0 = blockIdx.y * 128;
    float* C   = (blockIdx.y < 2) ? Qm : VP;
    const int coff = (blockIdx.y < 2) ? 0 : 256;

    float c[2][8][4] = {};
    {
        #pragma unroll
        for (int i = 0; i < 2; i++) {
            int sidx = t*2 + i; int row = sidx >> 2, seg = sidx & 3;
            CP16(sb + row*80 + seg*16,           A  + (size_t)(m0+row)*KAUG + seg*8);
            CP16(sb + 20480 + row*80 + seg*16,   Bw + (size_t)(n0+row)*KAUG + seg*8);
        }
        CPC();
    }
    const uint32_t aRowOff = (uint32_t)(wm*32 + (lane&15))*80 + ((lane>>4)&1)*16;
    const uint32_t bRowOff = (uint32_t)(wn*64 + (lane&7) + ((lane>>3)&1)*8)*80
                           + ((lane>>4)&1)*16;

    for (int ch = 0; ch < 24; ch++) {
        int buf = ch & 1;
        CPW0();
        __syncthreads();
        if (ch + 1 < 24) {
            int nb = buf ^ 1;
            #pragma unroll
            for (int i = 0; i < 2; i++) {
                int sidx = t*2 + i; int row = sidx >> 2, seg = sidx & 3;
                CP16(sb + nb*10240 + row*80 + seg*16,
                     A  + (size_t)(m0+row)*KAUG + (ch+1)*32 + seg*8);
                CP16(sb + 20480 + nb*10240 + row*80 + seg*16,
                     Bw + (size_t)(n0+row)*KAUG + (ch+1)*32 + seg*8);
            }
            CPC();
        }
        uint32_t aBase = sb + buf*10240 + aRowOff;
        uint32_t bBase = sb + 20480 + buf*10240 + bRowOff;
        #pragma unroll
        for (int ks = 0; ks < 2; ks++) {
            uint32_t a0,a1,a2,a3,a4,a5,a6,a7;
            ldsm4(aBase + ks*32,            a0,a1,a2,a3);
            ldsm4(aBase + 16*80 + ks*32,    a4,a5,a6,a7);
            #pragma unroll
            for (int p = 0; p < 4; p++) {
                uint32_t b0,b1,b2,b3;
                ldsm4(bBase + p*1280 + ks*32, b0,b1,b2,b3);
                mma16816(c[0][2*p+0], a0,a1,a2,a3, b0,b2);
                mma16816(c[0][2*p+1], a0,a1,a2,a3, b1,b3);
                mma16816(c[1][2*p+0], a4,a5,a6,a7, b0,b2);
                mma16816(c[1][2*p+1], a4,a5,a6,a7, b1,b3);
            }
        }
    }
    #pragma unroll
    for (int mi = 0; mi < 2; mi++)
        #pragma unroll
        for (int ni = 0; ni < 8; ni++) {
            int row = m0 + wm*32 + mi*16 + (lane>>2);
            int col = n0 - coff + wn*64 + ni*8 + 2*(lane&3);
            *(float2*)(C + (size_t)row*DD + col) =
                make_float2(c[mi][ni][0], c[mi][ni][1]);
            *(float2*)(C + (size_t)(row+8)*DD + col) =
                make_float2(c[mi][ni][2], c[mi][ni][3]);
        }
}

// ---------------- exact-Q 2-term attention (A=[Qh|Ql], B=Kh reused) ---------
#define AQ2_STRIDE 1040                        // 512 half + 16B pad
#define AQS2       (128*AQ2_STRIDE)            // 133120
#define KB2_OFF    AQS2
#define KST2       (128*80)                    // one 32-col K chunk
#define MRG2       (KB2_OFF + 2*KST2)          // 153600
#define SMEM_ATTN2 (MRG2 + 5120)               // 158720

__global__ __launch_bounds__(256) void attn2(const float* __restrict__ Qm_,
        const __half* __restrict__ yh_, const float* __restrict__ VP_,
        const float* __restrict__ bp, float* __restrict__ Og_)
{
    extern __shared__ __align__(128) char smem[];
    const uint32_t sb = smem_u32(smem);
    const int t = threadIdx.x, lane = t & 31, wid = t >> 5;
    const int wm = wid >> 1, wn = wid & 1;
    const int b = blockIdx.y, q0 = blockIdx.x * 128;

    const __half* Kb = yh_ + (size_t)b*NN*DD;

    // prologue: chunk 0 -> buf 0 (overlaps Q build)
    {
        #pragma unroll
        for (int i = 0; i < 2; i++) {
            int sidx = t*2 + i; int row = sidx >> 2, seg = sidx & 3;
            CP16(sb + KB2_OFF + row*80 + seg*16, Kb + (size_t)row*DD + seg*8);
        }
        CPC();
    }

    float* bp_s = (float*)(smem + MRG2 + 4096);
    if (t < 64) ((float4*)bp_s)[t] = ((const float4*)bp)[t];

    // build Q tile: [Qh(512B) | Ql(512B)] per row, pre-scaled (exact split of fp32 Q)
    const float* Qg = Qm_ + (size_t)(b*NN + q0)*DD;
    #pragma unroll 4
    for (int i = 0; i < 32; i++) {
        int e4 = t + i*256;
        int row = e4 >> 6, c4 = e4 & 63;
        float4 v = ((const float4*)Qg)[(size_t)row*64 + c4];
        v.x *= SCALE_F; v.y *= SCALE_F; v.z *= SCALE_F; v.w *= SCALE_F;
        __half h0=__float2half_rn(v.x), h1=__float2half_rn(v.y);
        __half h2=__float2half_rn(v.z), h3=__float2half_rn(v.w);
        __half2 H01=__halves2half2(h0,h1), H23=__halves2half2(h2,h3);
        __half2 L01=__halves2half2(__float2half_rn(v.x-__half2float(h0)),
                                   __float2half_rn(v.y-__half2float(h1)));
        __half2 L23=__halves2half2(__float2half_rn(v.z-__half2float(h2)),
                                   __float2half_rn(v.w-__half2float(h3)));
        char* base = smem + (size_t)row*AQ2_STRIDE + (size_t)c4*8;
        *(__half2*)(base)       = H01; *(__half2*)(base+4)   = H23;
        *(__half2*)(base+512)   = L01; *(__half2*)(base+516) = L23;
    }

    float c[2][8][4] = {};
    float rm[4], rs[4]; int ra[4];
    #pragma unroll
    for (int j = 0; j < 4; j++) { rm[j] = -3.0e38f; rs[j] = 0.f; ra[j] = 0; }

    const uint32_t aRowOff = (uint32_t)(wm*32 + (lane&15))*AQ2_STRIDE + ((lane>>4)&1)*16;
    const uint32_t bRowOff = (uint32_t)(wn*64 + (lane&7) + ((lane>>3)&1)*8)*80
                           + ((lane>>4)&1)*16;

    for (int kt = 0; kt < 32; kt++) {
        for (int ch = 0; ch < 8; ch++) {
            int glob = kt*8 + ch;
            int buf = glob & 1;
            CPW0();
            __syncthreads();
            if (glob + 1 < 256) {
                int nx = glob + 1;
                int nkt = nx >> 3, nch = nx & 7, nb = buf ^ 1;
                #pragma unroll
                for (int i = 0; i < 2; i++) {
                    int sidx = t*2 + i; int row = sidx >> 2, seg = sidx & 3;
                    CP16(sb + KB2_OFF + nb*KST2 + row*80 + seg*16,
                         Kb + (size_t)(nkt*128+row)*DD + nch*32 + seg*8);
                }
                CPC();
            }
            uint32_t aBase = sb + aRowOff + (uint32_t)ch*64;
            uint32_t bBase = sb + KB2_OFF + buf*KST2 + bRowOff;
            #pragma unroll
            for (int ks = 0; ks < 2; ks++) {
                uint32_t a0,a1,a2,a3,a4,a5,a6,a7;   // seg0 (Qh): two m-halves
                uint32_t e0,e1,e2,e3,e4r,e5,e6,e7;  // seg1 (Ql)
                ldsm4(aBase + ks*32,                        a0,a1,a2,a3);
                ldsm4(aBase + 16*AQ2_STRIDE + ks*32,        a4,a5,a6,a7);
                ldsm4(aBase + 512 + ks*32,                  e0,e1,e2,e3);
                ldsm4(aBase + 512 + 16*AQ2_STRIDE + ks*32,  e4r,e5,e6,e7);
                #pragma unroll
                for (int p = 0; p < 4; p++) {
                    uint32_t b0,b1,b2,b3;
                    ldsm4(bBase + p*1280 + ks*32, b0,b1,b2,b3);
                    mma16816(c[0][2*p+0], a0,a1,a2,a3, b0,b2);
                    mma16816(c[0][2*p+1], a0,a1,a2,a3, b1,b3);
                    mma16816(c[1][2*p+0], a4,a5,a6,a7, b0,b2);
                    mma16816(c[1][2*p+1], a4,a5,a6,a7, b1,b3);
                    mma16816(c[0][2*p+0], e0,e1,e2,e3, b0,b2);
                    mma16816(c[0][2*p+1], e0,e1,e2,e3, b1,b3);
                    mma16816(c[1][2*p+0], e4r,e5,e6,e7, b0,b2);
                    mma16816(c[1][2*p+1], e4r,e5,e6,e7, b1,b3);
                }
            }
        }

        // per-key-tile online reduction with argmax
        #pragma unroll
        for (int j = 0; j < 4; j++) {
            int mi = j >> 1, hr = (j & 1) * 2;
            float tm = -3.0e38f; int ta = 0;
            #pragma unroll
            for (int ni = 0; ni < 8; ni++) {
                float v0 = c[mi][ni][hr], v1 = c[mi][ni][hr+1];
                int col = ni*8 + 2*(lane&3);
                if (v0 > tm) { tm = v0; ta = col; }
                if (v1 > tm) { tm = v1; ta = col+1; }
            }
            #pragma unroll
            for (int off = 1; off <= 2; off <<= 1) {
                float om = __shfl_xor_sync(0xffffffffu, tm, off);
                int   oa = __shfl_xor_sync(0xffffffffu, ta, off);
                if (om > tm || (om == tm && oa < ta)) { tm = om; ta = oa; }
            }
            float ts = 0.f;
            #pragma unroll
            for (int ni = 0; ni < 8; ni++) {
                ts += __expf(c[mi][ni][hr]   - tm);
                ts += __expf(c[mi][ni][hr+1] - tm);
            }
            #pragma unroll
            for (int off = 1; off <= 2; off <<= 1)
                ts += __shfl_xor_sync(0xffffffffu, ts, off);
            if (tm > rm[j]) {
                rs[j] = rs[j]*__expf(rm[j]-tm) + ts;
                rm[j] = tm;
                ra[j] = kt*128 + wn*64 + ta;
            } else {
                rs[j] += ts*__expf(tm - rm[j]);
            }
        }
        #pragma unroll
        for (int mi = 0; mi < 2; mi++)
            #pragma unroll
            for (int ni = 0; ni < 8; ni++)
                #pragma unroll
                for (int r = 0; r < 4; r++) c[mi][ni][r] = 0.f;
    }

    // ---- merge n-halves, classify, write ----
    float* m_arr = (float*)(smem + MRG2);           // [256]
    float* s_arr = (float*)(smem + MRG2 + 1024);    // [256]
    int*   a_arr = (int*)  (smem + MRG2 + 2048);    // [256]
    float* p_arr = (float*)(smem + MRG2 + 3072);    // [128]
    int*   f_arr = (int*)  (smem + MRG2 + 3584);    // [128]
    if ((lane & 3) == 0) {
        #pragma unroll
        for (int j = 0; j < 4; j++) {
            int row = wm*32 + (j>>1)*16 + (j&1)*8 + (lane>>2);
            m_arr[wn*128 + row] = rm[j];
            s_arr[wn*128 + row] = rs[j];
            a_arr[wn*128 + row] = ra[j];
        }
    }
    __syncthreads();
    if (t < 128) {
        float m0v = m_arr[t], m1v = m_arr[128+t];
        float s0  = s_arr[t], s1  = s_arr[128+t];
        float mm  = fmaxf(m0v, m1v);
        float ss  = s0*__expf(m0v-mm) + s1*__expf(m1v-mm);
        int   aa  = (m0v >= m1v) ? a_arr[t] : a_arr[128+t];
        float pt  = 1.0f / ss;
        int cls;
        if (fabsf(pt - 0.6f) < BAND) {
            cls = 2;
            int slot = atomicAdd(&g_cnt, 1);
            if (slot < MTOT) g_list[slot] = b*NN + q0 + t;
        } else {
            cls = (pt >= 0.6f) ? 1 : 0;
        }
        p_arr[t] = pt; f_arr[t] = cls; a_arr[t] = aa;
    }
    __syncthreads();

    float* Og = Og_ + (size_t)(b*NN + q0)*DD;
    #pragma unroll 4
    for (int i = 0; i < 32; i++) {
        int e4 = t + i*256;
        int row = e4 >> 6, c4 = e4 & 63;
        int cls = f_arr[row];
        if (cls == 2) continue;                // rescue kernel writes this row
        float4 o = ((float4*)bp_s)[c4];
        if (cls == 1) {
            float p = p_arr[row];
            int   a = a_arr[row];
            float4 v = ((const float4*)(VP_ + (size_t)(b*NN + a)*DD))[c4];
            o = make_float4(v.x*p + o.x, v.y*p + o.y, v.z*p + o.z, v.w*p + o.w);
        }
        ((float4*)Og)[(size_t)row*64 + c4] = o;
    }
}

// ---------------- exact fp32 rescue for band rows ---------------------------
__global__ __launch_bounds__(256) void rescue(const float* __restrict__ Qm,
        const float* __restrict__ y, const float* __restrict__ VP,
        const float* __restrict__ bp, float* __restrict__ O)
{
    __shared__ float s_sm[4096];
    __shared__ float q_sm[256];
    __shared__ float red_m[8];
    __shared__ int   red_a[8];
    __shared__ float red_s[8];
    __shared__ float sh_m;
    __shared__ int   sh_a;
    __shared__ float sh_p;
    const int t = threadIdx.x, lane = t & 31, w = t >> 5;
    int cnt = g_cnt; if (cnt > MTOT) cnt = MTOT;

    for (int idx = blockIdx.x; idx < cnt; idx += gridDim.x) {
        int grow = g_list[idx];
        int b = grow >> 12;
        if (t < 64) ((float4*)q_sm)[t] = ((const float4*)(Qm + (size_t)grow*DD))[t];
        __syncthreads();

        const float* Kb = y + (size_t)b*NN*DD;
        float lm = -3.0e38f; int la = 0;
        for (int j = t; j < NN; j += 256) {
            const float4* kr = (const float4*)(Kb + (size_t)j*DD);
            float acc = 0.f;
            #pragma unroll
            for (int d = 0; d < 64; d++) {
                float4 kv = kr[d];
                float4 qv = ((const float4*)q_sm)[d];
                acc += qv.x*kv.x + qv.y*kv.y + qv.z*kv.z + qv.w*kv.w;
            }
            float s = acc * SCALE_F;
            s_sm[j] = s;
            if (s > lm) { lm = s; la = j; }
        }
        #pragma unroll
        for (int off = 16; off; off >>= 1) {
            float om = __shfl_xor_sync(0xffffffffu, lm, off);
            int   oa = __shfl_xor_sync(0xffffffffu, la, off);
            if (om > lm || (om == lm && oa < la)) { lm = om; la = oa; }
        }
        if (lane == 0) { red_m[w] = lm; red_a[w] = la; }
        __syncthreads();
        if (w == 0) {
            float m2 = (lane < 8) ? red_m[lane] : -3.0e38f;
            int   a2 = (lane < 8) ? red_a[lane] : 0;
            #pragma unroll
            for (int off = 4; off; off >>= 1) {
                float om = __shfl_xor_sync(0xffffffffu, m2, off);
                int   oa = __shfl_xor_sync(0xffffffffu, a2, off);
                if (om > m2 || (om == m2 && oa < a2)) { m2 = om; a2 = oa; }
            }
            if (lane == 0) { sh_m = m2; sh_a = a2; }
        }
        __syncthreads();
        float m = sh_m; int amax = sh_a;
        float ls = 0.f;
        for (int j = t; j < NN; j += 256) ls += __expf(s_sm[j] - m);
        #pragma unroll
        for (int off = 16; off; off >>= 1)
            ls += __shfl_xor_sync(0xffffffffu, ls, off);
        if (lane == 0) red_s[w] = ls;
        __syncthreads();
        if (t == 0) {
            float S = 0.f;
            #pragma unroll
            for (int i2 = 0; i2 < 8; i2++) S += red_s[i2];
            sh_p = 1.0f / S;
        }
        __syncthreads();
        float p = sh_p;
        if (p >= 0.6f)
            O[(size_t)grow*DD + t] = p * VP[(size_t)(b*NN + amax)*DD + t] + bp[t];
        else
            O[(size_t)grow*DD + t] = bp[t];
        __syncthreads();
    }
}

// ---------------------------------------------------------------------------
extern "C" void kernel_launch(void* const* d_in, const int* in_sizes, int n_in,
                              void* d_out, int out_size)
{
    const float* x  = (const float*)d_in[0];
    const float* y  = (const float*)d_in[1];
    const float* Wq = (const float*)d_in[2];
    const float* Wk = (const float*)d_in[3];
    const float* Wv = (const float*)d_in[4];
    const float* Wp = (const float*)d_in[5];
    const float* bp = (const float*)d_in[6];
    float* out = (float*)d_out;

    __half *Aaug, *yh, *Wt2;
    float *Qm, *VP, *M, *Wvp;
    void* cntp;
    cudaGetSymbolAddress((void**)&Aaug, g_Aaug);
    cudaGetSymbolAddress((void**)&yh,   g_yh);
    cudaGetSymbolAddress((void**)&Qm,   g_Qm);
    cudaGetSymbolAddress((void**)&VP,   g_VP);
    cudaGetSymbolAddress((void**)&M,    g_M);
    cudaGetSymbolAddress((void**)&Wvp,  g_Wvp);
    cudaGetSymbolAddress((void**)&Wt2,  g_Wt2);
    cudaGetSymbolAddress(&cntp,         g_cnt);

    cudaFuncSetAttribute(attn2,
                         cudaFuncAttributeMaxDynamicSharedMemorySize, SMEM_ATTN2);

    cudaMemsetAsync(cntp, 0, sizeof(int));

    prep_h<<<2048, 256>>>(y, yh);                       // attn K = fp16(y)
    gemm256_nt<<<dim3(4,4), 256>>>(Wq, Wk, M);          // M   = Wq Wk^T
    gemm256<<<dim3(4,4), 256>>>(Wv, Wp, Wvp);           // Wvp = Wv Wp
    prep_wt2<<<dim3(256,2), 256>>>(M, Wvp, Wt2);
    prep_aug<<<2048, 256>>>(x, Aaug);

    hgemm2<<<dim3(MTOT/128, 4), 256>>>(Aaug, Wt2, Qm, VP);  // Qm = xM, VP = xWvp

    attn2<<<dim3(NN/128, BB), 256, SMEM_ATTN2>>>(Qm, yh, VP, bp, out);
    rescue<<<256, 256>>>(Qm, y, VP, bp, out);
}

// round 10
// speedup vs baseline: 1.9475x; 1.3158x over previous
#include <cuda_runtime.h>
#include <cuda_fp16.h>
#include <math.h>
#include <stdint.h>

#define BB 4
#define NN 4096
#define DD 256
#define MTOT (BB*NN)          // 16384
#define KAUG 768              // 3-term split for projection GEMM
#define SCALE_F 0.17677669529663689f
#define BAND 2.0e-3f

// ---------------- static device scratch ------------------------------------
__device__ __half g_Aaug[(size_t)MTOT*KAUG];   // x augmented [h|h|l]
__device__ __half g_yh  [(size_t)MTOT*DD];     // y rounded to fp16 (attn K)
__device__ float  g_Qm  [(size_t)MTOT*DD];     // x . (Wq Wk^T)
__device__ float  g_VP  [(size_t)MTOT*DD];     // x . (Wv Wp)
__device__ __half g_Wt2 [(size_t)2*DD*KAUG];   // [M ; Wvp] split B-style, 512x768
__device__ int    g_cnt;
__device__ int    g_list[MTOT];
__device__ float  g_mval[MTOT];
__device__ double g_sumacc[MTOT];
__device__ unsigned long long g_maxp[MTOT];

// ---------------- PTX helpers ----------------------------------------------
__device__ __forceinline__ uint32_t smem_u32(const void* p){
    uint32_t a;
    asm("{ .reg .u64 t; cvta.to.shared.u64 t, %1; cvt.u32.u64 %0, t; }" : "=r"(a) : "l"(p));
    return a;
}
#define CP16(dst, src) \
    asm volatile("cp.async.cg.shared.global [%0], [%1], 16;" :: "r"(dst), "l"(src) : "memory")
#define CPC()  asm volatile("cp.async.commit_group;" ::: "memory")
#define CPW0() asm volatile("cp.async.wait_group 0;" ::: "memory")
#define CPW2() asm volatile("cp.async.wait_group 2;" ::: "memory")

__device__ __forceinline__ void ldsm4(uint32_t a, uint32_t& r0, uint32_t& r1,
                                      uint32_t& r2, uint32_t& r3){
    asm volatile("ldmatrix.sync.aligned.m8n8.x4.shared.b16 {%0,%1,%2,%3}, [%4];"
        : "=r"(r0), "=r"(r1), "=r"(r2), "=r"(r3) : "r"(a));
}
__device__ __forceinline__ void mma16816(float* c,
        uint32_t a0, uint32_t a1, uint32_t a2, uint32_t a3,
        uint32_t b0, uint32_t b1){
    asm volatile("mma.sync.aligned.m16n8k16.row.col.f32.f16.f16.f32 "
        "{%0,%1,%2,%3}, {%4,%5,%6,%7}, {%8,%9}, {%0,%1,%2,%3};"
        : "+f"(c[0]), "+f"(c[1]), "+f"(c[2]), "+f"(c[3])
        : "r"(a0), "r"(a1), "r"(a2), "r"(a3), "r"(b0), "r"(b1));
}

// ---------------- fused input prep: x -> Aaug [h|h|l], y -> fp16 ------------
__global__ void prep_xy(const float* __restrict__ x, const float* __restrict__ y,
                        __half* __restrict__ Aaug, __half* __restrict__ yh)
{
    const size_t totalx = (size_t)MTOT * 64;
    const size_t total  = totalx * 2;
    for (size_t i = (size_t)blockIdx.x*blockDim.x + threadIdx.x; i < total;
         i += (size_t)gridDim.x*blockDim.x) {
        if (i < totalx) {
            size_t row = i >> 6; int c4 = (int)(i & 63);
            float4 v = ((const float4*)x)[i];
            __half h0=__float2half_rn(v.x), h1=__float2half_rn(v.y);
            __half h2=__float2half_rn(v.z), h3=__float2half_rn(v.w);
            __half2 H01=__halves2half2(h0,h1), H23=__halves2half2(h2,h3);
            __half2 L01=__halves2half2(__float2half_rn(v.x-__half2float(h0)),
                                       __float2half_rn(v.y-__half2float(h1)));
            __half2 L23=__halves2half2(__float2half_rn(v.z-__half2float(h2)),
                                       __float2half_rn(v.w-__half2float(h3)));
            __half* base = Aaug + row*KAUG + c4*4;
            ((__half2*)base)[0] = H01; ((__half2*)base)[1] = H23;
            ((__half2*)(base+256))[0] = H01; ((__half2*)(base+256))[1] = H23;
            ((__half2*)(base+512))[0] = L01; ((__half2*)(base+512))[1] = L23;
        } else {
            size_t j = i - totalx;
            float4 v = ((const float4*)y)[j];
            ((__half2*)yh)[j*2]   = __halves2half2(__float2half_rn(v.x), __float2half_rn(v.y));
            ((__half2*)yh)[j*2+1] = __halves2half2(__float2half_rn(v.z), __float2half_rn(v.w));
        }
    }
}

// ---------------- weight GEMMs with split epilogue --------------------------
// M = Wq @ Wk^T ; split written directly to Wt2 rows [0,256)
__global__ __launch_bounds__(256) void wgemm_qk(const float* __restrict__ Wq,
                                                const float* __restrict__ Wk,
                                                __half* __restrict__ Wt2)
{
    __shared__ float As[64][17];
    __shared__ float Ws[16][64];
    const int t  = threadIdx.x;
    const int tx = t & 15, ty = t >> 4;
    const int m0 = blockIdx.x * 64, n0 = blockIdx.y * 64;
    const int lr = t >> 2, lc = (t & 3) * 4;
    float acc[4][4] = {};
    for (int kk = 0; kk < 256; kk += 16) {
        float4 av = *(const float4*)(Wq + (size_t)(m0 + lr) * 256 + kk + lc);
        As[lr][lc+0]=av.x; As[lr][lc+1]=av.y; As[lr][lc+2]=av.z; As[lr][lc+3]=av.w;
        #pragma unroll
        for (int i = 0; i < 4; i++)
            Ws[ty][tx*4+i] = Wk[(size_t)(n0 + tx*4 + i) * 256 + kk + ty];
        __syncthreads();
        #pragma unroll
        for (int c = 0; c < 16; c++) {
            float a0=As[ty*4+0][c], a1=As[ty*4+1][c], a2=As[ty*4+2][c], a3=As[ty*4+3][c];
            float4 w = *(const float4*)&Ws[c][tx*4];
            acc[0][0]+=a0*w.x; acc[0][1]+=a0*w.y; acc[0][2]+=a0*w.z; acc[0][3]+=a0*w.w;
            acc[1][0]+=a1*w.x; acc[1][1]+=a1*w.y; acc[1][2]+=a1*w.z; acc[1][3]+=a1*w.w;
            acc[2][0]+=a2*w.x; acc[2][1]+=a2*w.y; acc[2][2]+=a2*w.z; acc[2][3]+=a2*w.w;
            acc[3][0]+=a3*w.x; acc[3][1]+=a3*w.y; acc[3][2]+=a3*w.z; acc[3][3]+=a3*w.w;
        }
        __syncthreads();
    }
    #pragma unroll
    for (int j2 = 0; j2 < 4; j2++) {
        int i = m0 + ty*4 + j2;
        #pragma unroll
        for (int c = 0; c < 4; c++) {
            int n = n0 + tx*4 + c;
            float v = acc[j2][c];
            __half h = __float2half_rn(v);
            __half l = __float2half_rn(v - __half2float(h));
            __half* dst = Wt2 + (size_t)n*KAUG;
            dst[i] = h; dst[256 + i] = l; dst[512 + i] = h;
        }
    }
}

// Wvp = Wv @ Wp ; split written directly to Wt2 rows [256,512)
__global__ __launch_bounds__(256) void wgemm_vp(const float* __restrict__ Wv,
                                                const float* __restrict__ Wp,
                                                __half* __restrict__ Wt2)
{
    __shared__ float As[64][17];
    __shared__ float Ws[16][64];
    const int t  = threadIdx.x;
    const int tx = t & 15, ty = t >> 4;
    const int m0 = blockIdx.x * 64, n0 = blockIdx.y * 64;
    const int lr = t >> 2, lc = (t & 3) * 4;
    float acc[4][4] = {};
    for (int kk = 0; kk < 256; kk += 16) {
        float4 av = *(const float4*)(Wv + (size_t)(m0 + lr) * 256 + kk + lc);
        As[lr][lc+0]=av.x; As[lr][lc+1]=av.y; As[lr][lc+2]=av.z; As[lr][lc+3]=av.w;
        float4 wv = *(const float4*)(Wp + (size_t)(kk + ty) * 256 + n0 + tx * 4);
        *(float4*)&Ws[ty][tx*4] = wv;
        __syncthreads();
        #pragma unroll
        for (int c = 0; c < 16; c++) {
            float a0=As[ty*4+0][c], a1=As[ty*4+1][c], a2=As[ty*4+2][c], a3=As[ty*4+3][c];
            float4 w = *(const float4*)&Ws[c][tx*4];
            acc[0][0]+=a0*w.x; acc[0][1]+=a0*w.y; acc[0][2]+=a0*w.z; acc[0][3]+=a0*w.w;
            acc[1][0]+=a1*w.x; acc[1][1]+=a1*w.y; acc[1][2]+=a1*w.z; acc[1][3]+=a1*w.w;
            acc[2][0]+=a2*w.x; acc[2][1]+=a2*w.y; acc[2][2]+=a2*w.z; acc[2][3]+=a2*w.w;
            acc[3][0]+=a3*w.x; acc[3][1]+=a3*w.y; acc[3][2]+=a3*w.z; acc[3][3]+=a3*w.w;
        }
        __syncthreads();
    }
    #pragma unroll
    for (int j2 = 0; j2 < 4; j2++) {
        int i = m0 + ty*4 + j2;
        #pragma unroll
        for (int c = 0; c < 4; c++) {
            int n = n0 + tx*4 + c;
            float v = acc[j2][c];
            __half h = __float2half_rn(v);
            __half l = __float2half_rn(v - __half2float(h));
            __half* dst = Wt2 + (size_t)(256 + n)*KAUG;
            dst[i] = h; dst[256 + i] = l; dst[512 + i] = h;
        }
    }
}

// ---------------- fused HMMA GEMM: [Qm | VP] = Aaug . Wt2^T -----------------
__global__ __launch_bounds__(256) void hgemm2(const __half* __restrict__ A,
                                              const __half* __restrict__ Bw,
                                              float* __restrict__ Qm,
                                              float* __restrict__ VP)
{
    __shared__ __align__(16) char sm[4*10240];
    const uint32_t sb = smem_u32(sm);
    const int t = threadIdx.x, lane = t & 31, wid = t >> 5;
    const int wm = wid >> 1, wn = wid & 1;
    const int m0 = blockIdx.x * 128, n0 = blockIdx.y * 128;
    float* C   = (blockIdx.y < 2) ? Qm : VP;
    const int coff = (blockIdx.y < 2) ? 0 : 256;

    float c[2][8][4] = {};
    {
        #pragma unroll
        for (int i = 0; i < 2; i++) {
            int sidx = t*2 + i; int row = sidx >> 2, seg = sidx & 3;
            CP16(sb + row*80 + seg*16,           A  + (size_t)(m0+row)*KAUG + seg*8);
            CP16(sb + 20480 + row*80 + seg*16,   Bw + (size_t)(n0+row)*KAUG + seg*8);
        }
        CPC();
    }
    const uint32_t aRowOff = (uint32_t)(wm*32 + (lane&15))*80 + ((lane>>4)&1)*16;
    const uint32_t bRowOff = (uint32_t)(wn*64 + (lane&7) + ((lane>>3)&1)*8)*80
                           + ((lane>>4)&1)*16;

    for (int ch = 0; ch < 24; ch++) {
        int buf = ch & 1;
        CPW0();
        __syncthreads();
        if (ch + 1 < 24) {
            int nb = buf ^ 1;
            #pragma unroll
            for (int i = 0; i < 2; i++) {
                int sidx = t*2 + i; int row = sidx >> 2, seg = sidx & 3;
                CP16(sb + nb*10240 + row*80 + seg*16,
                     A  + (size_t)(m0+row)*KAUG + (ch+1)*32 + seg*8);
                CP16(sb + 20480 + nb*10240 + row*80 + seg*16,
                     Bw + (size_t)(n0+row)*KAUG + (ch+1)*32 + seg*8);
            }
            CPC();
        }
        uint32_t aBase = sb + buf*10240 + aRowOff;
        uint32_t bBase = sb + 20480 + buf*10240 + bRowOff;
        #pragma unroll
        for (int ks = 0; ks < 2; ks++) {
            uint32_t a0,a1,a2,a3,a4,a5,a6,a7;
            ldsm4(aBase + ks*32,            a0,a1,a2,a3);
            ldsm4(aBase + 16*80 + ks*32,    a4,a5,a6,a7);
            #pragma unroll
            for (int p = 0; p < 4; p++) {
                uint32_t b0,b1,b2,b3;
                ldsm4(bBase + p*1280 + ks*32, b0,b1,b2,b3);
                mma16816(c[0][2*p+0], a0,a1,a2,a3, b0,b2);
                mma16816(c[0][2*p+1], a0,a1,a2,a3, b1,b3);
                mma16816(c[1][2*p+0], a4,a5,a6,a7, b0,b2);
                mma16816(c[1][2*p+1], a4,a5,a6,a7, b1,b3);
            }
        }
    }
    #pragma unroll
    for (int mi = 0; mi < 2; mi++)
        #pragma unroll
        for (int ni = 0; ni < 8; ni++) {
            int row = m0 + wm*32 + mi*16 + (lane>>2);
            int col = n0 - coff + wn*64 + ni*8 + 2*(lane&3);
            *(float2*)(C + (size_t)row*DD + col) =
                make_float2(c[mi][ni][0], c[mi][ni][1]);
            *(float2*)(C + (size_t)(row+8)*DD + col) =
                make_float2(c[mi][ni][2], c[mi][ni][3]);
        }
}

// ---------------- exact-Q 2-term attention, 4-stage 64-dim chunks -----------
#define AQ2_STRIDE 1040                        // 512 half + 16B pad
#define AQS2       (128*AQ2_STRIDE)            // 133120
#define KB2_OFF    AQS2
#define KST2       (128*144)                   // one 64-dim chunk (128 keys)
#define MRG2       (KB2_OFF + 4*KST2)          // 206848
#define SMEM_ATTN2 (MRG2 + 5120)               // 211968

__global__ __launch_bounds__(256) void attn2(const float* __restrict__ Qm_,
        const __half* __restrict__ yh_, const float* __restrict__ VP_,
        const float* __restrict__ bp, float* __restrict__ Og_)
{
    extern __shared__ __align__(128) char smem[];
    const uint32_t sb = smem_u32(smem);
    const int t = threadIdx.x, lane = t & 31, wid = t >> 5;
    const int wm = wid >> 1, wn = wid & 1;
    const int b = blockIdx.y, q0 = blockIdx.x * 128;

    const __half* Kb = yh_ + (size_t)b*NN*DD;

    // prologue: 3 chunks in flight (kt 0, dim-chunks 0..2)
    #pragma unroll
    for (int st = 0; st < 3; st++) {
        #pragma unroll
        for (int i = 0; i < 4; i++) {
            int sidx = t*4 + i; int row = sidx >> 3, seg = sidx & 7;
            CP16(sb + KB2_OFF + st*KST2 + row*144 + seg*16,
                 Kb + (size_t)row*DD + st*64 + seg*8);
        }
        CPC();
    }

    float* bp_s = (float*)(smem + MRG2 + 4096);
    if (t < 64) ((float4*)bp_s)[t] = ((const float4*)bp)[t];

    // build Q tile: [Qh(512B) | Ql(512B)] per row, pre-scaled exact split
    const float* Qg = Qm_ + (size_t)(b*NN + q0)*DD;
    #pragma unroll 4
    for (int i = 0; i < 32; i++) {
        int e4 = t + i*256;
        int row = e4 >> 6, c4 = e4 & 63;
        float4 v = ((const float4*)Qg)[(size_t)row*64 + c4];
        v.x *= SCALE_F; v.y *= SCALE_F; v.z *= SCALE_F; v.w *= SCALE_F;
        __half h0=__float2half_rn(v.x), h1=__float2half_rn(v.y);
        __half h2=__float2half_rn(v.z), h3=__float2half_rn(v.w);
        __half2 H01=__halves2half2(h0,h1), H23=__halves2half2(h2,h3);
        __half2 L01=__halves2half2(__float2half_rn(v.x-__half2float(h0)),
                                   __float2half_rn(v.y-__half2float(h1)));
        __half2 L23=__halves2half2(__float2half_rn(v.z-__half2float(h2)),
                                   __float2half_rn(v.w-__half2float(h3)));
        char* base = smem + (size_t)row*AQ2_STRIDE + (size_t)c4*8;
        *(__half2*)(base)       = H01; *(__half2*)(base+4)   = H23;
        *(__half2*)(base+512)   = L01; *(__half2*)(base+516) = L23;
    }

    float c[2][8][4] = {};
    float rm[4], rs[4]; int ra[4];
    #pragma unroll
    for (int j = 0; j < 4; j++) { rm[j] = -3.0e38f; rs[j] = 0.f; ra[j] = 0; }

    const uint32_t aRowOff = (uint32_t)(wm*32 + (lane&15))*AQ2_STRIDE + ((lane>>4)&1)*16;
    const uint32_t bRowOff = (uint32_t)(wn*64 + (lane&7) + ((lane>>3)&1)*8)*144
                           + ((lane>>4)&1)*16;

    for (int idx = 0; idx < 128; idx++) {
        CPW2();                       // chunk idx resident (<=2 groups pending)
        __syncthreads();
        if (idx + 3 < 128) {
            int nx = idx + 3, nkt = nx >> 2, nch = nx & 3, nb = nx & 3;
            #pragma unroll
            for (int i = 0; i < 4; i++) {
                int sidx = t*4 + i; int row = sidx >> 3, seg = sidx & 7;
                CP16(sb + KB2_OFF + nb*KST2 + row*144 + seg*16,
                     Kb + (size_t)(nkt*128+row)*DD + nch*64 + seg*8);
            }
            CPC();
        }
        uint32_t aBase = sb + aRowOff + (uint32_t)(idx & 3)*128;
        uint32_t bBase = sb + KB2_OFF + (idx & 3)*KST2 + bRowOff;
        #pragma unroll
        for (int ks = 0; ks < 4; ks++) {
            uint32_t a0,a1,a2,a3,a4,a5,a6,a7;   // Qh, two m-halves
            uint32_t e0,e1,e2,e3,e4r,e5,e6,e7;  // Ql
            ldsm4(aBase + ks*32,                        a0,a1,a2,a3);
            ldsm4(aBase + 16*AQ2_STRIDE + ks*32,        a4,a5,a6,a7);
            ldsm4(aBase + 512 + ks*32,                  e0,e1,e2,e3);
            ldsm4(aBase + 512 + 16*AQ2_STRIDE + ks*32,  e4r,e5,e6,e7);
            #pragma unroll
            for (int p = 0; p < 4; p++) {
                uint32_t b0,b1,b2,b3;
                ldsm4(bBase + p*2304 + ks*32, b0,b1,b2,b3);
                mma16816(c[0][2*p+0], a0,a1,a2,a3, b0,b2);
                mma16816(c[0][2*p+1], a0,a1,a2,a3, b1,b3);
                mma16816(c[1][2*p+0], a4,a5,a6,a7, b0,b2);
                mma16816(c[1][2*p+1], a4,a5,a6,a7, b1,b3);
                mma16816(c[0][2*p+0], e0,e1,e2,e3, b0,b2);
                mma16816(c[0][2*p+1], e0,e1,e2,e3, b1,b3);
                mma16816(c[1][2*p+0], e4r,e5,e6,e7, b0,b2);
                mma16816(c[1][2*p+1], e4r,e5,e6,e7, b1,b3);
            }
        }

        if ((idx & 3) == 3) {
            int kt = idx >> 2;
            #pragma unroll
            for (int j = 0; j < 4; j++) {
                int mi = j >> 1, hr = (j & 1) * 2;
                float tm = -3.0e38f; int ta = 0;
                #pragma unroll
                for (int ni = 0; ni < 8; ni++) {
                    float v0 = c[mi][ni][hr], v1 = c[mi][ni][hr+1];
                    int col = ni*8 + 2*(lane&3);
                    if (v0 > tm) { tm = v0; ta = col; }
                    if (v1 > tm) { tm = v1; ta = col+1; }
                }
                #pragma unroll
                for (int off = 1; off <= 2; off <<= 1) {
                    float om = __shfl_xor_sync(0xffffffffu, tm, off);
                    int   oa = __shfl_xor_sync(0xffffffffu, ta, off);
                    if (om > tm || (om == tm && oa < ta)) { tm = om; ta = oa; }
                }
                float ts = 0.f;
                #pragma unroll
                for (int ni = 0; ni < 8; ni++) {
                    ts += __expf(c[mi][ni][hr]   - tm);
                    ts += __expf(c[mi][ni][hr+1] - tm);
                }
                #pragma unroll
                for (int off = 1; off <= 2; off <<= 1)
                    ts += __shfl_xor_sync(0xffffffffu, ts, off);
                if (tm > rm[j]) {
                    rs[j] = rs[j]*__expf(rm[j]-tm) + ts;
                    rm[j] = tm;
                    ra[j] = kt*128 + wn*64 + ta;
                } else {
                    rs[j] += ts*__expf(tm - rm[j]);
                }
            }
            #pragma unroll
            for (int mi = 0; mi < 2; mi++)
                #pragma unroll
                for (int ni = 0; ni < 8; ni++)
                    #pragma unroll
                    for (int r = 0; r < 4; r++) c[mi][ni][r] = 0.f;
        }
    }

    // ---- merge n-halves, classify, write ----
    float* m_arr = (float*)(smem + MRG2);           // [256]
    float* s_arr = (float*)(smem + MRG2 + 1024);    // [256]
    int*   a_arr = (int*)  (smem + MRG2 + 2048);    // [256]
    float* p_arr = (float*)(smem + MRG2 + 3072);    // [128]
    int*   f_arr = (int*)  (smem + MRG2 + 3584);    // [128]
    if ((lane & 3) == 0) {
        #pragma unroll
        for (int j = 0; j < 4; j++) {
            int row = wm*32 + (j>>1)*16 + (j&1)*8 + (lane>>2);
            m_arr[wn*128 + row] = rm[j];
            s_arr[wn*128 + row] = rs[j];
            a_arr[wn*128 + row] = ra[j];
        }
    }
    __syncthreads();
    if (t < 128) {
        float m0v = m_arr[t], m1v = m_arr[128+t];
        float s0  = s_arr[t], s1  = s_arr[128+t];
        float mm  = fmaxf(m0v, m1v);
        float ss  = s0*__expf(m0v-mm) + s1*__expf(m1v-mm);
        int   aa  = (m0v >= m1v) ? a_arr[t] : a_arr[128+t];
        float pt  = 1.0f / ss;
        int cls;
        if (fabsf(pt - 0.6f) < BAND) {
            int slot = atomicAdd(&g_cnt, 1);
            if (slot < MTOT) {
                g_list[slot]   = b*NN + q0 + t;
                g_mval[slot]   = mm;
                g_sumacc[slot] = 0.0;
                g_maxp[slot]   = 0ull;
                cls = 2;
            } else {
                cls = (pt >= 0.6f) ? 1 : 0;   // overflow fallback
            }
        } else {
            cls = (pt >= 0.6f) ? 1 : 0;
        }
        p_arr[t] = pt; f_arr[t] = cls; a_arr[t] = aa;
    }
    __syncthreads();

    float* Og = Og_ + (size_t)(b*NN + q0)*DD;
    #pragma unroll 4
    for (int i = 0; i < 32; i++) {
        int e4 = t + i*256;
        int row = e4 >> 6, c4 = e4 & 63;
        int cls = f_arr[row];
        if (cls == 2) continue;                // finalize writes this row
        float4 o = ((float4*)bp_s)[c4];
        if (cls == 1) {
            float p = p_arr[row];
            int   a = a_arr[row];
            float4 v = ((const float4*)(VP_ + (size_t)(b*NN + a)*DD))[c4];
            o = make_float4(v.x*p + o.x, v.y*p + o.y, v.z*p + o.z, v.w*p + o.w);
        }
        ((float4*)Og)[(size_t)row*64 + c4] = o;
    }
}

// ---------------- shared-K exact rescue: partial sums per key block ---------
// grid (64 key-blocks, BB batches); K block (64 keys x 256 f32) staged once.
#define KSM_STRIDE 260
#define RS_SMEM (64*KSM_STRIDE*4 + 1024 + 64)

__global__ __launch_bounds__(256) void rescue_sum(const float* __restrict__ Qm,
                                                  const float* __restrict__ y)
{
    extern __shared__ __align__(16) char rsm[];
    float* k_sm = (float*)rsm;                         // 64 x 260
    float* q_sm = (float*)(rsm + 64*KSM_STRIDE*4);     // 256
    double* s_acc = (double*)(rsm + 64*KSM_STRIDE*4 + 1024);
    unsigned long long* s_max = (unsigned long long*)(s_acc + 1);

    const int t = threadIdx.x, lane = t & 31;
    const int kb = blockIdx.x, b = blockIdx.y;
    const int key0 = kb * 64;

    const float* Kb = y + ((size_t)b*NN + key0)*DD;
    for (int i = t; i < 64*64; i += 256) {
        int key = i >> 6, c4 = i & 63;
        *(float4*)&k_sm[key*KSM_STRIDE + c4*4] = ((const float4*)Kb)[i];
    }

    int cnt = g_cnt; if (cnt > MTOT) cnt = MTOT;
    const int key  = t >> 2, part = t & 3;
    const float* krow = k_sm + key*KSM_STRIDE + part*64;

    for (int idx = 0; idx < cnt; idx++) {
        int grow = g_list[idx];
        if ((grow >> 12) != b) continue;               // uniform branch
        if (t == 0) { *s_acc = 0.0; *s_max = 0ull; }
        if (t < 64) ((float4*)q_sm)[t] = ((const float4*)(Qm + (size_t)grow*DD))[t];
        __syncthreads();

        const float* qp = q_sm + part*64;
        float acc = 0.f;
        #pragma unroll 16
        for (int d = 0; d < 64; d++) acc += qp[d] * krow[d];
        acc += __shfl_xor_sync(0xffffffffu, acc, 1);
        acc += __shfl_xor_sync(0xffffffffu, acc, 2);
        float s = acc * SCALE_F;

        float mval = g_mval[idx];
        double exd = 0.0;
        unsigned long long pk = 0ull;
        if ((t & 3) == 0) {
            exd = (double)__expf(s - mval);
            uint32_t u = __float_as_uint(s);
            u = (s >= 0.f) ? (u | 0x80000000u) : ~u;
            pk = ((unsigned long long)u << 32) | (uint32_t)(key0 + key);
        }
        #pragma unroll
        for (int off = 4; off <= 16; off <<= 1) {
            exd += __shfl_xor_sync(0xffffffffu, exd, off);
            unsigned long long op = __shfl_xor_sync(0xffffffffu, pk, off);
            if (op > pk) pk = op;
        }
        if (lane == 0) {
            atomicAdd(s_acc, exd);
            atomicMax(s_max, pk);
        }
        __syncthreads();
        if (t == 0) {
            atomicAdd(&g_sumacc[idx], *s_acc);
            atomicMax(&g_maxp[idx], *s_max);
        }
    }
}

// ---------------- finalize band rows ----------------------------------------
__global__ __launch_bounds__(256) void finalize(const float* __restrict__ VP,
        const float* __restrict__ bp, float* __restrict__ O)
{
    int cnt = g_cnt; if (cnt > MTOT) cnt = MTOT;
    const int t = threadIdx.x;
    for (int idx = blockIdx.x; idx < cnt; idx += gridDim.x) {
        int grow = g_list[idx];
        int b = grow >> 12;
        double S = g_sumacc[idx];
        unsigned long long pk = g_maxp[idx];
        uint32_t u = (uint32_t)(pk >> 32);
        int amax = (int)(pk & 0xffffffffu);
        uint32_t ru = (u & 0x80000000u) ? (u & 0x7fffffffu) : ~u;
        float smax = __uint_as_float(ru);
        double p = exp((double)smax - (double)g_mval[idx]) / S;
        float out;
        if (p >= 0.6) out = (float)p * VP[((size_t)(b*NN) + amax)*DD + t] + bp[t];
        else          out = bp[t];
        O[(size_t)grow*DD + t] = out;
    }
}

// ---------------------------------------------------------------------------
extern "C" void kernel_launch(void* const* d_in, const int* in_sizes, int n_in,
                              void* d_out, int out_size)
{
    const float* x  = (const float*)d_in[0];
    const float* y  = (const float*)d_in[1];
    const float* Wq = (const float*)d_in[2];
    const float* Wk = (const float*)d_in[3];
    const float* Wv = (const float*)d_in[4];
    const float* Wp = (const float*)d_in[5];
    const float* bp = (const float*)d_in[6];
    float* out = (float*)d_out;

    __half *Aaug, *yh, *Wt2;
    float *Qm, *VP;
    void* cntp;
    cudaGetSymbolAddress((void**)&Aaug, g_Aaug);
    cudaGetSymbolAddress((void**)&yh,   g_yh);
    cudaGetSymbolAddress((void**)&Qm,   g_Qm);
    cudaGetSymbolAddress((void**)&VP,   g_VP);
    cudaGetSymbolAddress((void**)&Wt2,  g_Wt2);
    cudaGetSymbolAddress(&cntp,         g_cnt);

    cudaFuncSetAttribute(attn2,
                         cudaFuncAttributeMaxDynamicSharedMemorySize, SMEM_ATTN2);
    cudaFuncSetAttribute(rescue_sum,
                         cudaFuncAttributeMaxDynamicSharedMemorySize, RS_SMEM);

    cudaMemsetAsync(cntp, 0, sizeof(int));

    prep_xy<<<4096, 256>>>(x, y, Aaug, yh);
    wgemm_qk<<<dim3(4,4), 256>>>(Wq, Wk, Wt2);
    wgemm_vp<<<dim3(4,4), 256>>>(Wv, Wp, Wt2);

    hgemm2<<<dim3(MTOT/128, 4), 256>>>(Aaug, Wt2, Qm, VP);

    attn2<<<dim3(NN/128, BB), 256, SMEM_ATTN2>>>(Qm, yh, VP, bp, out);
    rescue_sum<<<dim3(64, BB), 256, RS_SMEM>>>(Qm, y);
    finalize<<<128, 256>>>(VP, bp, out);
}

// round 11
// speedup vs baseline: 2.3191x; 1.1908x over previous
#include <cuda_runtime.h>
#include <cuda_fp16.h>
#include <math.h>
#include <stdint.h>

#define BB 4
#define NN 4096
#define DD 256
#define MTOT (BB*NN)          // 16384
#define KAUG 768              // 3-term split for projection GEMM
#define SCALE_F 0.17677669529663689f
#define BAND 4.0e-3f

// ---------------- static device scratch ------------------------------------
__device__ __half g_Aaug[(size_t)MTOT*KAUG];   // x augmented [h|h|l]
__device__ __half g_yh  [(size_t)MTOT*DD];     // y rounded to fp16 (attn K)
__device__ float  g_Qm  [(size_t)MTOT*DD];     // x . (Wq Wk^T)
__device__ float  g_VP  [(size_t)MTOT*DD];     // x . (Wv Wp)
__device__ __half g_Wt2 [(size_t)2*DD*KAUG];   // [M ; Wvp] split B-style, 512x768
__device__ int    g_cnt;
__device__ int    g_list[MTOT];
__device__ float  g_mval[MTOT];
__device__ double g_sumacc[MTOT];
__device__ unsigned long long g_maxp[MTOT];

// ---------------- PTX helpers ----------------------------------------------
__device__ __forceinline__ uint32_t smem_u32(const void* p){
    uint32_t a;
    asm("{ .reg .u64 t; cvta.to.shared.u64 t, %1; cvt.u32.u64 %0, t; }" : "=r"(a) : "l"(p));
    return a;
}
#define CP16(dst, src) \
    asm volatile("cp.async.cg.shared.global [%0], [%1], 16;" :: "r"(dst), "l"(src) : "memory")
#define CPC()  asm volatile("cp.async.commit_group;" ::: "memory")
#define CPW0() asm volatile("cp.async.wait_group 0;" ::: "memory")
#define CPW2() asm volatile("cp.async.wait_group 2;" ::: "memory")

__device__ __forceinline__ void ldsm4(uint32_t a, uint32_t& r0, uint32_t& r1,
                                      uint32_t& r2, uint32_t& r3){
    asm volatile("ldmatrix.sync.aligned.m8n8.x4.shared.b16 {%0,%1,%2,%3}, [%4];"
        : "=r"(r0), "=r"(r1), "=r"(r2), "=r"(r3) : "r"(a));
}
__device__ __forceinline__ void mma16816(float* c,
        uint32_t a0, uint32_t a1, uint32_t a2, uint32_t a3,
        uint32_t b0, uint32_t b1){
    asm volatile("mma.sync.aligned.m16n8k16.row.col.f32.f16.f16.f32 "
        "{%0,%1,%2,%3}, {%4,%5,%6,%7}, {%8,%9}, {%0,%1,%2,%3};"
        : "+f"(c[0]), "+f"(c[1]), "+f"(c[2]), "+f"(c[3])
        : "r"(a0), "r"(a1), "r"(a2), "r"(a3), "r"(b0), "r"(b1));
}

// ---------------- fused input prep: x -> Aaug [h|h|l], y -> fp16 ------------
__global__ void prep_xy(const float* __restrict__ x, const float* __restrict__ y,
                        __half* __restrict__ Aaug, __half* __restrict__ yh)
{
    const size_t totalx = (size_t)MTOT * 64;
    const size_t total  = totalx * 2;
    for (size_t i = (size_t)blockIdx.x*blockDim.x + threadIdx.x; i < total;
         i += (size_t)gridDim.x*blockDim.x) {
        if (i < totalx) {
            size_t row = i >> 6; int c4 = (int)(i & 63);
            float4 v = ((const float4*)x)[i];
            __half h0=__float2half_rn(v.x), h1=__float2half_rn(v.y);
            __half h2=__float2half_rn(v.z), h3=__float2half_rn(v.w);
            __half2 H01=__halves2half2(h0,h1), H23=__halves2half2(h2,h3);
            __half2 L01=__halves2half2(__float2half_rn(v.x-__half2float(h0)),
                                       __float2half_rn(v.y-__half2float(h1)));
            __half2 L23=__halves2half2(__float2half_rn(v.z-__half2float(h2)),
                                       __float2half_rn(v.w-__half2float(h3)));
            __half* base = Aaug + row*KAUG + c4*4;
            ((__half2*)base)[0] = H01; ((__half2*)base)[1] = H23;
            ((__half2*)(base+256))[0] = H01; ((__half2*)(base+256))[1] = H23;
            ((__half2*)(base+512))[0] = L01; ((__half2*)(base+512))[1] = L23;
        } else {
            size_t j = i - totalx;
            float4 v = ((const float4*)y)[j];
            ((__half2*)yh)[j*2]   = __halves2half2(__float2half_rn(v.x), __float2half_rn(v.y));
            ((__half2*)yh)[j*2+1] = __halves2half2(__float2half_rn(v.z), __float2half_rn(v.w));
        }
    }
}

// ---------------- weight GEMMs with split epilogue --------------------------
// M = Wq @ Wk^T ; split written directly to Wt2 rows [0,256)
__global__ __launch_bounds__(256) void wgemm_qk(const float* __restrict__ Wq,
                                                const float* __restrict__ Wk,
                                                __half* __restrict__ Wt2)
{
    __shared__ float As[64][17];
    __shared__ float Ws[16][64];
    const int t  = threadIdx.x;
    const int tx = t & 15, ty = t >> 4;
    const int m0 = blockIdx.x * 64, n0 = blockIdx.y * 64;
    const int lr = t >> 2, lc = (t & 3) * 4;
    float acc[4][4] = {};
    for (int kk = 0; kk < 256; kk += 16) {
        float4 av = *(const float4*)(Wq + (size_t)(m0 + lr) * 256 + kk + lc);
        As[lr][lc+0]=av.x; As[lr][lc+1]=av.y; As[lr][lc+2]=av.z; As[lr][lc+3]=av.w;
        #pragma unroll
        for (int i = 0; i < 4; i++)
            Ws[ty][tx*4+i] = Wk[(size_t)(n0 + tx*4 + i) * 256 + kk + ty];
        __syncthreads();
        #pragma unroll
        for (int c = 0; c < 16; c++) {
            float a0=As[ty*4+0][c], a1=As[ty*4+1][c], a2=As[ty*4+2][c], a3=As[ty*4+3][c];
            float4 w = *(const float4*)&Ws[c][tx*4];
            acc[0][0]+=a0*w.x; acc[0][1]+=a0*w.y; acc[0][2]+=a0*w.z; acc[0][3]+=a0*w.w;
            acc[1][0]+=a1*w.x; acc[1][1]+=a1*w.y; acc[1][2]+=a1*w.z; acc[1][3]+=a1*w.w;
            acc[2][0]+=a2*w.x; acc[2][1]+=a2*w.y; acc[2][2]+=a2*w.z; acc[2][3]+=a2*w.w;
            acc[3][0]+=a3*w.x; acc[3][1]+=a3*w.y; acc[3][2]+=a3*w.z; acc[3][3]+=a3*w.w;
        }
        __syncthreads();
    }
    #pragma unroll
    for (int j2 = 0; j2 < 4; j2++) {
        int i = m0 + ty*4 + j2;
        #pragma unroll
        for (int c = 0; c < 4; c++) {
            int n = n0 + tx*4 + c;
            float v = acc[j2][c];
            __half h = __float2half_rn(v);
            __half l = __float2half_rn(v - __half2float(h));
            __half* dst = Wt2 + (size_t)n*KAUG;
            dst[i] = h; dst[256 + i] = l; dst[512 + i] = h;
        }
    }
}

// Wvp = Wv @ Wp ; split written directly to Wt2 rows [256,512)
__global__ __launch_bounds__(256) void wgemm_vp(const float* __restrict__ Wv,
                                                const float* __restrict__ Wp,
                                                __half* __restrict__ Wt2)
{
    __shared__ float As[64][17];
    __shared__ float Ws[16][64];
    const int t  = threadIdx.x;
    const int tx = t & 15, ty = t >> 4;
    const int m0 = blockIdx.x * 64, n0 = blockIdx.y * 64;
    const int lr = t >> 2, lc = (t & 3) * 4;
    float acc[4][4] = {};
    for (int kk = 0; kk < 256; kk += 16) {
        float4 av = *(const float4*)(Wv + (size_t)(m0 + lr) * 256 + kk + lc);
        As[lr][lc+0]=av.x; As[lr][lc+1]=av.y; As[lr][lc+2]=av.z; As[lr][lc+3]=av.w;
        float4 wv = *(const float4*)(Wp + (size_t)(kk + ty) * 256 + n0 + tx * 4);
        *(float4*)&Ws[ty][tx*4] = wv;
        __syncthreads();
        #pragma unroll
        for (int c = 0; c < 16; c++) {
            float a0=As[ty*4+0][c], a1=As[ty*4+1][c], a2=As[ty*4+2][c], a3=As[ty*4+3][c];
            float4 w = *(const float4*)&Ws[c][tx*4];
            acc[0][0]+=a0*w.x; acc[0][1]+=a0*w.y; acc[0][2]+=a0*w.z; acc[0][3]+=a0*w.w;
            acc[1][0]+=a1*w.x; acc[1][1]+=a1*w.y; acc[1][2]+=a1*w.z; acc[1][3]+=a1*w.w;
            acc[2][0]+=a2*w.x; acc[2][1]+=a2*w.y; acc[2][2]+=a2*w.z; acc[2][3]+=a2*w.w;
            acc[3][0]+=a3*w.x; acc[3][1]+=a3*w.y; acc[3][2]+=a3*w.z; acc[3][3]+=a3*w.w;
        }
        __syncthreads();
    }
    #pragma unroll
    for (int j2 = 0; j2 < 4; j2++) {
        int i = m0 + ty*4 + j2;
        #pragma unroll
        for (int c = 0; c < 4; c++) {
            int n = n0 + tx*4 + c;
            float v = acc[j2][c];
            __half h = __float2half_rn(v);
            __half l = __float2half_rn(v - __half2float(h));
            __half* dst = Wt2 + (size_t)(256 + n)*KAUG;
            dst[i] = h; dst[256 + i] = l; dst[512 + i] = h;
        }
    }
}

// ---------------- fused HMMA GEMM: [Qm | VP] = Aaug . Wt2^T -----------------
__global__ __launch_bounds__(256) void hgemm2(const __half* __restrict__ A,
                                              const __half* __restrict__ Bw,
                                              float* __restrict__ Qm,
                                              float* __restrict__ VP)
{
    __shared__ __align__(16) char sm[4*10240];
    const uint32_t sb = smem_u32(sm);
    const int t = threadIdx.x, lane = t & 31, wid = t >> 5;
    const int wm = wid >> 1, wn = wid & 1;
    const int m0 = blockIdx.x * 128, n0 = blockIdx.y * 128;
    float* C   = (blockIdx.y < 2) ? Qm : VP;
    const int coff = (blockIdx.y < 2) ? 0 : 256;

    float c[2][8][4] = {};
    {
        #pragma unroll
        for (int i = 0; i < 2; i++) {
            int sidx = t*2 + i; int row = sidx >> 2, seg = sidx & 3;
            CP16(sb + row*80 + seg*16,           A  + (size_t)(m0+row)*KAUG + seg*8);
            CP16(sb + 20480 + row*80 + seg*16,   Bw + (size_t)(n0+row)*KAUG + seg*8);
        }
        CPC();
    }
    const uint32_t aRowOff = (uint32_t)(wm*32 + (lane&15))*80 + ((lane>>4)&1)*16;
    const uint32_t bRowOff = (uint32_t)(wn*64 + (lane&7) + ((lane>>3)&1)*8)*80
                           + ((lane>>4)&1)*16;

    for (int ch = 0; ch < 24; ch++) {
        int buf = ch & 1;
        CPW0();
        __syncthreads();
        if (ch + 1 < 24) {
            int nb = buf ^ 1;
            #pragma unroll
            for (int i = 0; i < 2; i++) {
                int sidx = t*2 + i; int row = sidx >> 2, seg = sidx & 3;
                CP16(sb + nb*10240 + row*80 + seg*16,
                     A  + (size_t)(m0+row)*KAUG + (ch+1)*32 + seg*8);
                CP16(sb + 20480 + nb*10240 + row*80 + seg*16,
                     Bw + (size_t)(n0+row)*KAUG + (ch+1)*32 + seg*8);
            }
            CPC();
        }
        uint32_t aBase = sb + buf*10240 + aRowOff;
        uint32_t bBase = sb + 20480 + buf*10240 + bRowOff;
        #pragma unroll
        for (int ks = 0; ks < 2; ks++) {
            uint32_t a0,a1,a2,a3,a4,a5,a6,a7;
            ldsm4(aBase + ks*32,            a0,a1,a2,a3);
            ldsm4(aBase + 16*80 + ks*32,    a4,a5,a6,a7);
            #pragma unroll
            for (int p = 0; p < 4; p++) {
                uint32_t b0,b1,b2,b3;
                ldsm4(bBase + p*1280 + ks*32, b0,b1,b2,b3);
                mma16816(c[0][2*p+0], a0,a1,a2,a3, b0,b2);
                mma16816(c[0][2*p+1], a0,a1,a2,a3, b1,b3);
                mma16816(c[1][2*p+0], a4,a5,a6,a7, b0,b2);
                mma16816(c[1][2*p+1], a4,a5,a6,a7, b1,b3);
            }
        }
    }
    #pragma unroll
    for (int mi = 0; mi < 2; mi++)
        #pragma unroll
        for (int ni = 0; ni < 8; ni++) {
            int row = m0 + wm*32 + mi*16 + (lane>>2);
            int col = n0 - coff + wn*64 + ni*8 + 2*(lane&3);
            *(float2*)(C + (size_t)row*DD + col) =
                make_float2(c[mi][ni][0], c[mi][ni][1]);
            *(float2*)(C + (size_t)(row+8)*DD + col) =
                make_float2(c[mi][ni][2], c[mi][ni][3]);
        }
}

// ---------------- 1-term attention (Qh.Kh), 4-stage 64-dim chunks -----------
#define AQ2_STRIDE 528                         // 256 half + 16B pad
#define AQS2       (128*AQ2_STRIDE)            // 67584
#define KB2_OFF    AQS2
#define KST2       (128*144)                   // one 64-dim chunk (128 keys)
#define MRG2       (KB2_OFF + 4*KST2)          // 141312
#define SMEM_ATTN2 (MRG2 + 5120)               // 146432

__global__ __launch_bounds__(256) void attn2(const float* __restrict__ Qm_,
        const __half* __restrict__ yh_, const float* __restrict__ VP_,
        const float* __restrict__ bp, float* __restrict__ Og_)
{
    extern __shared__ __align__(128) char smem[];
    const uint32_t sb = smem_u32(smem);
    const int t = threadIdx.x, lane = t & 31, wid = t >> 5;
    const int wm = wid >> 1, wn = wid & 1;
    const int b = blockIdx.y, q0 = blockIdx.x * 128;

    const __half* Kb = yh_ + (size_t)b*NN*DD;

    // prologue: 3 chunks in flight (kt 0, dim-chunks 0..2)
    #pragma unroll
    for (int st = 0; st < 3; st++) {
        #pragma unroll
        for (int i = 0; i < 4; i++) {
            int sidx = t*4 + i; int row = sidx >> 3, seg = sidx & 7;
            CP16(sb + KB2_OFF + st*KST2 + row*144 + seg*16,
                 Kb + (size_t)row*DD + st*64 + seg*8);
        }
        CPC();
    }

    float* bp_s = (float*)(smem + MRG2 + 4096);
    if (t < 64) ((float4*)bp_s)[t] = ((const float4*)bp)[t];

    // build Qh tile (pre-scaled, rounded to fp16)
    const float* Qg = Qm_ + (size_t)(b*NN + q0)*DD;
    #pragma unroll 4
    for (int i = 0; i < 32; i++) {
        int e4 = t + i*256;
        int row = e4 >> 6, c4 = e4 & 63;
        float4 v = ((const float4*)Qg)[(size_t)row*64 + c4];
        __half2 H01 = __halves2half2(__float2half_rn(v.x*SCALE_F),
                                     __float2half_rn(v.y*SCALE_F));
        __half2 H23 = __halves2half2(__float2half_rn(v.z*SCALE_F),
                                     __float2half_rn(v.w*SCALE_F));
        char* base = smem + (size_t)row*AQ2_STRIDE + (size_t)c4*8;
        *(__half2*)(base)   = H01;
        *(__half2*)(base+4) = H23;
    }

    float c[2][8][4] = {};
    float rm[4], rs[4]; int ra[4];
    #pragma unroll
    for (int j = 0; j < 4; j++) { rm[j] = -3.0e38f; rs[j] = 0.f; ra[j] = 0; }

    const uint32_t aRowOff = (uint32_t)(wm*32 + (lane&15))*AQ2_STRIDE + ((lane>>4)&1)*16;
    const uint32_t bRowOff = (uint32_t)(wn*64 + (lane&7) + ((lane>>3)&1)*8)*144
                           + ((lane>>4)&1)*16;

    for (int idx = 0; idx < 128; idx++) {
        CPW2();                       // chunk idx resident (<=2 groups pending)
        __syncthreads();
        if (idx + 3 < 128) {
            int nx = idx + 3, nkt = nx >> 2, nch = nx & 3, nb = nx & 3;
            #pragma unroll
            for (int i = 0; i < 4; i++) {
                int sidx = t*4 + i; int row = sidx >> 3, seg = sidx & 7;
                CP16(sb + KB2_OFF + nb*KST2 + row*144 + seg*16,
                     Kb + (size_t)(nkt*128+row)*DD + nch*64 + seg*8);
            }
            CPC();
        }
        uint32_t aBase = sb + aRowOff + (uint32_t)(idx & 3)*128;
        uint32_t bBase = sb + KB2_OFF + (idx & 3)*KST2 + bRowOff;
        #pragma unroll
        for (int ks = 0; ks < 4; ks++) {
            uint32_t a0,a1,a2,a3,a4,a5,a6,a7;
            ldsm4(aBase + ks*32,                  a0,a1,a2,a3);
            ldsm4(aBase + 16*AQ2_STRIDE + ks*32,  a4,a5,a6,a7);
            #pragma unroll
            for (int p = 0; p < 4; p++) {
                uint32_t b0,b1,b2,b3;
                ldsm4(bBase + p*2304 + ks*32, b0,b1,b2,b3);
                mma16816(c[0][2*p+0], a0,a1,a2,a3, b0,b2);
                mma16816(c[0][2*p+1], a0,a1,a2,a3, b1,b3);
                mma16816(c[1][2*p+0], a4,a5,a6,a7, b0,b2);
                mma16816(c[1][2*p+1], a4,a5,a6,a7, b1,b3);
            }
        }

        if ((idx & 3) == 3) {
            int kt = idx >> 2;
            #pragma unroll
            for (int j = 0; j < 4; j++) {
                int mi = j >> 1, hr = (j & 1) * 2;
                float tm = -3.0e38f; int ta = 0;
                #pragma unroll
                for (int ni = 0; ni < 8; ni++) {
                    float v0 = c[mi][ni][hr], v1 = c[mi][ni][hr+1];
                    int col = ni*8 + 2*(lane&3);
                    if (v0 > tm) { tm = v0; ta = col; }
                    if (v1 > tm) { tm = v1; ta = col+1; }
                }
                #pragma unroll
                for (int off = 1; off <= 2; off <<= 1) {
                    float om = __shfl_xor_sync(0xffffffffu, tm, off);
                    int   oa = __shfl_xor_sync(0xffffffffu, ta, off);
                    if (om > tm || (om == tm && oa < ta)) { tm = om; ta = oa; }
                }
                float ts = 0.f;
                #pragma unroll
                for (int ni = 0; ni < 8; ni++) {
                    ts += __expf(c[mi][ni][hr]   - tm);
                    ts += __expf(c[mi][ni][hr+1] - tm);
                }
                #pragma unroll
                for (int off = 1; off <= 2; off <<= 1)
                    ts += __shfl_xor_sync(0xffffffffu, ts, off);
                if (tm > rm[j]) {
                    rs[j] = rs[j]*__expf(rm[j]-tm) + ts;
                    rm[j] = tm;
                    ra[j] = kt*128 + wn*64 + ta;
                } else {
                    rs[j] += ts*__expf(tm - rm[j]);
                }
            }
            #pragma unroll
            for (int mi = 0; mi < 2; mi++)
                #pragma unroll
                for (int ni = 0; ni < 8; ni++)
                    #pragma unroll
                    for (int r = 0; r < 4; r++) c[mi][ni][r] = 0.f;
        }
    }

    // ---- merge n-halves, classify, write ----
    float* m_arr = (float*)(smem + MRG2);           // [256]
    float* s_arr = (float*)(smem + MRG2 + 1024);    // [256]
    int*   a_arr = (int*)  (smem + MRG2 + 2048);    // [256]
    float* p_arr = (float*)(smem + MRG2 + 3072);    // [128]
    int*   f_arr = (int*)  (smem + MRG2 + 3584);    // [128]
    if ((lane & 3) == 0) {
        #pragma unroll
        for (int j = 0; j < 4; j++) {
            int row = wm*32 + (j>>1)*16 + (j&1)*8 + (lane>>2);
            m_arr[wn*128 + row] = rm[j];
            s_arr[wn*128 + row] = rs[j];
            a_arr[wn*128 + row] = ra[j];
        }
    }
    __syncthreads();
    if (t < 128) {
        float m0v = m_arr[t], m1v = m_arr[128+t];
        float s0  = s_arr[t], s1  = s_arr[128+t];
        float mm  = fmaxf(m0v, m1v);
        float ss  = s0*__expf(m0v-mm) + s1*__expf(m1v-mm);
        int   aa  = (m0v >= m1v) ? a_arr[t] : a_arr[128+t];
        float pt  = 1.0f / ss;
        int cls;
        if (fabsf(pt - 0.6f) < BAND) {
            int slot = atomicAdd(&g_cnt, 1);
            if (slot < MTOT) {
                g_list[slot]   = b*NN + q0 + t;
                g_mval[slot]   = mm;
                g_sumacc[slot] = 0.0;
                g_maxp[slot]   = 0ull;
                cls = 2;
            } else {
                cls = (pt >= 0.6f) ? 1 : 0;   // overflow fallback
            }
        } else {
            cls = (pt >= 0.6f) ? 1 : 0;
        }
        p_arr[t] = pt; f_arr[t] = cls; a_arr[t] = aa;
    }
    __syncthreads();

    float* Og = Og_ + (size_t)(b*NN + q0)*DD;
    #pragma unroll 4
    for (int i = 0; i < 32; i++) {
        int e4 = t + i*256;
        int row = e4 >> 6, c4 = e4 & 63;
        int cls = f_arr[row];
        if (cls == 2) continue;                // finalize writes this row
        float4 o = ((float4*)bp_s)[c4];
        if (cls == 1) {
            float p = p_arr[row];
            int   a = a_arr[row];
            float4 v = ((const float4*)(VP_ + (size_t)(b*NN + a)*DD))[c4];
            o = make_float4(v.x*p + o.x, v.y*p + o.y, v.z*p + o.z, v.w*p + o.w);
        }
        ((float4*)Og)[(size_t)row*64 + c4] = o;
    }
}

// ---------------- shared-K exact rescue: partial sums per key block ---------
#define KSM_STRIDE 260
#define RS_SMEM (64*KSM_STRIDE*4 + 1024 + 64)

__global__ __launch_bounds__(256) void rescue_sum(const float* __restrict__ Qm,
                                                  const float* __restrict__ y)
{
    extern __shared__ __align__(16) char rsm[];
    float* k_sm = (float*)rsm;                         // 64 x 260
    float* q_sm = (float*)(rsm + 64*KSM_STRIDE*4);     // 256
    double* s_acc = (double*)(rsm + 64*KSM_STRIDE*4 + 1024);
    unsigned long long* s_max = (unsigned long long*)(s_acc + 1);

    const int t = threadIdx.x, lane = t & 31;
    const int kb = blockIdx.x, b = blockIdx.y;
    const int key0 = kb * 64;

    const float* Kb = y + ((size_t)b*NN + key0)*DD;
    for (int i = t; i < 64*64; i += 256) {
        int key = i >> 6, c4 = i & 63;
        *(float4*)&k_sm[key*KSM_STRIDE + c4*4] = ((const float4*)Kb)[i];
    }

    int cnt = g_cnt; if (cnt > MTOT) cnt = MTOT;
    const int key  = t >> 2, part = t & 3;
    const float* krow = k_sm + key*KSM_STRIDE + part*64;

    for (int idx = 0; idx < cnt; idx++) {
        int grow = g_list[idx];
        if ((grow >> 12) != b) continue;               // uniform branch
        if (t == 0) { *s_acc = 0.0; *s_max = 0ull; }
        if (t < 64) ((float4*)q_sm)[t] = ((const float4*)(Qm + (size_t)grow*DD))[t];
        __syncthreads();

        const float* qp = q_sm + part*64;
        float acc = 0.f;
        #pragma unroll 16
        for (int d = 0; d < 64; d++) acc += qp[d] * krow[d];
        acc += __shfl_xor_sync(0xffffffffu, acc, 1);
        acc += __shfl_xor_sync(0xffffffffu, acc, 2);
        float s = acc * SCALE_F;

        float mval = g_mval[idx];
        double exd = 0.0;
        unsigned long long pk = 0ull;
        if ((t & 3) == 0) {
            exd = (double)__expf(s - mval);
            uint32_t u = __float_as_uint(s);
            u = (s >= 0.f) ? (u | 0x80000000u) : ~u;
            pk = ((unsigned long long)u << 32) | (uint32_t)(key0 + key);
        }
        #pragma unroll
        for (int off = 4; off <= 16; off <<= 1) {
            exd += __shfl_xor_sync(0xffffffffu, exd, off);
            unsigned long long op = __shfl_xor_sync(0xffffffffu, pk, off);
            if (op > pk) pk = op;
        }
        if (lane == 0) {
            atomicAdd(s_acc, exd);
            atomicMax(s_max, pk);
        }
        __syncthreads();
        if (t == 0) {
            atomicAdd(&g_sumacc[idx], *s_acc);
            atomicMax(&g_maxp[idx], *s_max);
        }
    }
}

// ---------------- finalize band rows ----------------------------------------
__global__ __launch_bounds__(256) void finalize(const float* __restrict__ VP,
        const float* __restrict__ bp, float* __restrict__ O)
{
    int cnt = g_cnt; if (cnt > MTOT) cnt = MTOT;
    const int t = threadIdx.x;
    for (int idx = blockIdx.x; idx < cnt; idx += gridDim.x) {
        int grow = g_list[idx];
        int b = grow >> 12;
        double S = g_sumacc[idx];
        unsigned long long pk = g_maxp[idx];
        uint32_t u = (uint32_t)(pk >> 32);
        int amax = (int)(pk & 0xffffffffu);
        uint32_t ru = (u & 0x80000000u) ? (u & 0x7fffffffu) : ~u;
        float smax = __uint_as_float(ru);
        double p = exp((double)smax - (double)g_mval[idx]) / S;
        float out;
        if (p >= 0.6) out = (float)p * VP[((size_t)(b*NN) + amax)*DD + t] + bp[t];
        else          out = bp[t];
        O[(size_t)grow*DD + t] = out;
    }
}

// ---------------------------------------------------------------------------
extern "C" void kernel_launch(void* const* d_in, const int* in_sizes, int n_in,
                              void* d_out, int out_size)
{
    const float* x  = (const float*)d_in[0];
    const float* y  = (const float*)d_in[1];
    const float* Wq = (const float*)d_in[2];
    const float* Wk = (const float*)d_in[3];
    const float* Wv = (const float*)d_in[4];
    const float* Wp = (const float*)d_in[5];
    const float* bp = (const float*)d_in[6];
    float* out = (float*)d_out;

    __half *Aaug, *yh, *Wt2;
    float *Qm, *VP;
    void* cntp;
    cudaGetSymbolAddress((void**)&Aaug, g_Aaug);
    cudaGetSymbolAddress((void**)&yh,   g_yh);
    cudaGetSymbolAddress((void**)&Qm,   g_Qm);
    cudaGetSymbolAddress((void**)&VP,   g_VP);
    cudaGetSymbolAddress((void**)&Wt2,  g_Wt2);
    cudaGetSymbolAddress(&cntp,         g_cnt);

    cudaFuncSetAttribute(attn2,
                         cudaFuncAttributeMaxDynamicSharedMemorySize, SMEM_ATTN2);
    cudaFuncSetAttribute(rescue_sum,
                         cudaFuncAttributeMaxDynamicSharedMemorySize, RS_SMEM);

    cudaMemsetAsync(cntp, 0, sizeof(int));

    prep_xy<<<4096, 256>>>(x, y, Aaug, yh);
    wgemm_qk<<<dim3(4,4), 256>>>(Wq, Wk, Wt2);
    wgemm_vp<<<dim3(4,4), 256>>>(Wv, Wp, Wt2);

    hgemm2<<<dim3(MTOT/128, 4), 256>>>(Aaug, Wt2, Qm, VP);

    attn2<<<dim3(NN/128, BB), 256, SMEM_ATTN2>>>(Qm, yh, VP, bp, out);
    rescue_sum<<<dim3(64, BB), 256, RS_SMEM>>>(Qm, y);
    finalize<<<128, 256>>>(VP, bp, out);
}